// round 9
// baseline (speedup 1.0000x reference)
#include <cuda_runtime.h>
#include <cuda_bf16.h>
#include <cstdint>

typedef unsigned long long ull;
typedef unsigned int u32;
typedef unsigned short u16;

// ---------------- constants ----------------
#define NDICT   50000
#define DIN     256
#define DH      256
#define NGATE   1024
#define BB      256
#define SS      512
#define NBLK    128
#define BT      16                  // batch rows per CTA

// ---- scan smem (bytes); pitches conflict-free for ldmatrix
#define AP 264
#define HP 264
#define SM_UHI   0
#define SM_H0HI (SM_UHI + 128 * AP * 2)           // 67584
#define SM_H0LO (SM_H0HI + BT * HP * 2)           // +8448
#define SM_H1HI (SM_H0LO + BT * HP * 2)
#define SM_H1LO (SM_H1HI + BT * HP * 2)
#define SM_TOTAL (SM_H1LO + BT * HP * 2)          // 101376 B

// ---- ew_gemm2 smem
#define EP 72
#define EW_AH 0
#define EW_AL (EW_AH + 128 * EP * 2)
#define EW_BH (EW_AL + 128 * EP * 2)
#define EW_BL (EW_BH + 128 * EP * 2)
#define EW_BIAS (EW_BL + 128 * EP * 2)
#define EW_SMEM (EW_BIAS + 128 * 4)

// ---------------- device scratch ----------------
__device__ float g_EW[(size_t)NDICT * NGATE];  // Emb@W^T + bias, cols permuted j*4+type
__device__ u32   g_hsplit[2 * 2 * BB * DH];    // [buf][dir][b][k] packed bf16 hi|lo<<16
__device__ float g_h[2 * DH * BB];             // final h [dir][j][b] fp32
__device__ int   g_wordsT[SS * BB];
__device__ unsigned g_flags[2 * 16 * 64];      // [dir][bt-group][js*8]

// ---------------- helpers ----------------
__device__ __forceinline__ u32 smem_u32(const void* p) {
    u32 a; asm("{ .reg .u64 t; cvta.to.shared.u64 t, %1; cvt.u32.u64 %0, t; }"
               : "=r"(a) : "l"(p));
    return a;
}
__device__ __forceinline__ float fsig(float x) {
    float e = __expf(-x);
    return __fdividef(1.0f, 1.0f + e);
}
__device__ __forceinline__ float ftanh(float x) {
    float ax = fabsf(x);
    float e  = __expf(-2.0f * ax);
    float r  = __fdividef(1.0f - e, 1.0f + e);
    return copysignf(r, x);
}
__device__ __forceinline__ void ldsm4(u32* r, u32 addr) {
    asm volatile("ldmatrix.sync.aligned.m8n8.x4.shared.b16 {%0,%1,%2,%3}, [%4];"
                 : "=r"(r[0]), "=r"(r[1]), "=r"(r[2]), "=r"(r[3]) : "r"(addr));
}
__device__ __forceinline__ void mma16816(float* c, const u32* a, const u32* b) {
    asm volatile("mma.sync.aligned.m16n8k16.row.col.f32.bf16.bf16.f32 "
                 "{%0,%1,%2,%3}, {%4,%5,%6,%7}, {%8,%9}, {%0,%1,%2,%3};"
                 : "+f"(c[0]), "+f"(c[1]), "+f"(c[2]), "+f"(c[3])
                 : "r"(a[0]), "r"(a[1]), "r"(a[2]), "r"(a[3]), "r"(b[0]), "r"(b[1]));
}
__device__ __forceinline__ void bsplit(float x, u16& hi, u16& lo) {
    __nv_bfloat16 h = __float2bfloat16(x);
    __nv_bfloat16 l = __float2bfloat16(x - __bfloat162float(h));
    hi = __bfloat16_as_ushort(h);
    lo = __bfloat16_as_ushort(l);
}

// ---------------- kernel 0: reset ----------------
__global__ void reset_kernel(const int* __restrict__ words) {
    int idx = blockIdx.x * blockDim.x + threadIdx.x;
    if (idx < 2 * 16 * 64) g_flags[idx] = 0u;
    for (int i = idx; i < 2 * BB * DH; i += gridDim.x * blockDim.x) g_hsplit[i] = 0u;
    for (int i = idx; i < SS * BB; i += gridDim.x * blockDim.x) {
        int s = i >> 8, b = i & 255;
        g_wordsT[i] = words[b * SS + s];
    }
}

// ---------------- kernel 1: EW = Emb @ W^T (+bias), split-bf16 HMMA ----------------
__global__ __launch_bounds__(256) void ew_gemm2(const float* __restrict__ Emb,
                                                const float* __restrict__ W,
                                                const float* __restrict__ bias) {
    extern __shared__ __align__(16) char esm[];
    u32 sb = smem_u32(esm);
    float* biasp = (float*)(esm + EW_BIAS);

    int tid = threadIdx.x;
    int w = tid >> 5, lid = tid & 31;
    int mbase = blockIdx.x * 128;
    int nbase = blockIdx.y * 128;
    int wm = (w & 3) * 32, wn = (w >> 2) * 64;

    if (tid < 128) {
        int colp = nbase + tid;
        biasp[tid] = bias[(colp & 3) * 256 + (colp >> 2)];
    }

    int idx4 = lid >> 3, r8 = lid & 7;
    u32 aoff0 = (u32)(((wm + (idx4 & 1) * 8 + r8) * EP + (idx4 >> 1) * 8) * 2);
    u32 aoff1 = aoff0 + (u32)(16 * EP * 2);
    u32 boffB = (u32)(((wn + (idx4 >> 1) * 8 + r8) * EP + (idx4 & 1) * 8) * 2);

    float acc[2][8][4];
#pragma unroll
    for (int mt = 0; mt < 2; mt++)
#pragma unroll
        for (int n8 = 0; n8 < 8; n8++)
#pragma unroll
            for (int q = 0; q < 4; q++) acc[mt][n8][q] = 0.f;

    for (int kb = 0; kb < 4; kb++) {
        int k0 = kb * 64;
        for (int i = tid; i < 128 * 16; i += 256) {
            int row = i >> 4, kq = (i & 15) * 4;
            int va = mbase + row;
            float4 v = make_float4(0.f, 0.f, 0.f, 0.f);
            if (va < NDICT) v = *(const float4*)&Emb[(size_t)va * DIN + k0 + kq];
            u16 h0, l0, h1, l1, h2, l2, h3, l3;
            bsplit(v.x, h0, l0); bsplit(v.y, h1, l1);
            bsplit(v.z, h2, l2); bsplit(v.w, h3, l3);
            u32* ah = (u32*)(esm + EW_AH + (row * EP + kq) * 2);
            u32* al = (u32*)(esm + EW_AL + (row * EP + kq) * 2);
            ah[0] = (u32)h0 | ((u32)h1 << 16); ah[1] = (u32)h2 | ((u32)h3 << 16);
            al[0] = (u32)l0 | ((u32)l1 << 16); al[1] = (u32)l2 | ((u32)l3 << 16);
        }
        for (int i = tid; i < 128 * 16; i += 256) {
            int row = i >> 4, kq = (i & 15) * 4;
            int colp = nbase + row;
            int grow = (colp & 3) * 256 + (colp >> 2);
            float4 v = *(const float4*)&W[(size_t)grow * DIN + k0 + kq];
            u16 h0, l0, h1, l1, h2, l2, h3, l3;
            bsplit(v.x, h0, l0); bsplit(v.y, h1, l1);
            bsplit(v.z, h2, l2); bsplit(v.w, h3, l3);
            u32* bh = (u32*)(esm + EW_BH + (row * EP + kq) * 2);
            u32* bl = (u32*)(esm + EW_BL + (row * EP + kq) * 2);
            bh[0] = (u32)h0 | ((u32)h1 << 16); bh[1] = (u32)h2 | ((u32)h3 << 16);
            bl[0] = (u32)l0 | ((u32)l1 << 16); bl[1] = (u32)l2 | ((u32)l3 << 16);
        }
        __syncthreads();

#pragma unroll
        for (int kt = 0; kt < 4; kt++) {
            u32 koff = (u32)(kt * 32);
            u32 a0h[4], a1h[4], a0l[4], a1l[4];
            ldsm4(a0h, sb + EW_AH + aoff0 + koff);
            ldsm4(a1h, sb + EW_AH + aoff1 + koff);
            ldsm4(a0l, sb + EW_AL + aoff0 + koff);
            ldsm4(a1l, sb + EW_AL + aoff1 + koff);
#pragma unroll
            for (int p = 0; p < 4; p++) {
                u32 po = (u32)(p * 16 * EP * 2);
                u32 bh[4], bl[4];
                ldsm4(bh, sb + EW_BH + boffB + po + koff);
                ldsm4(bl, sb + EW_BL + boffB + po + koff);
                mma16816(acc[0][2 * p + 0], a0h, bh + 0);
                mma16816(acc[0][2 * p + 1], a0h, bh + 2);
                mma16816(acc[1][2 * p + 0], a1h, bh + 0);
                mma16816(acc[1][2 * p + 1], a1h, bh + 2);
                mma16816(acc[0][2 * p + 0], a0h, bl + 0);
                mma16816(acc[0][2 * p + 1], a0h, bl + 2);
                mma16816(acc[1][2 * p + 0], a1h, bl + 0);
                mma16816(acc[1][2 * p + 1], a1h, bl + 2);
                mma16816(acc[0][2 * p + 0], a0l, bh + 0);
                mma16816(acc[0][2 * p + 1], a0l, bh + 2);
                mma16816(acc[1][2 * p + 0], a1l, bh + 0);
                mma16816(acc[1][2 * p + 1], a1l, bh + 2);
            }
        }
        __syncthreads();
    }

#pragma unroll
    for (int mt = 0; mt < 2; mt++) {
#pragma unroll
        for (int n8 = 0; n8 < 8; n8++) {
            int nl = wn + n8 * 8 + (lid & 3) * 2;
            int col = nbase + nl;
            float b0 = biasp[nl], b1 = biasp[nl + 1];
            int r0 = mbase + wm + mt * 16 + (lid >> 2);
            if (r0 < NDICT)
                *(float2*)&g_EW[(size_t)r0 * NGATE + col] =
                    make_float2(acc[mt][n8][0] + b0, acc[mt][n8][1] + b1);
            if (r0 + 8 < NDICT)
                *(float2*)&g_EW[(size_t)(r0 + 8) * NGATE + col] =
                    make_float2(acc[mt][n8][2] + b0, acc[mt][n8][3] + b1);
        }
    }
}

// ---------------- kernel 2: persistent scan — dual-direction staggered HMMA ----------------
// grid = 128 CTAs: batch-tile(16, 16 rows) x gate-slice(8, 32 j); each CTA runs BOTH dirs
// Per dir-phase: gates[128 rows(w*32+type*8+jl), 16 b] = Uhi.hhi + Uhi.hlo
__global__ __launch_bounds__(128, 1) void scan_kernel(const float* __restrict__ U) {
    extern __shared__ __align__(16) char smem[];
    u32 sbase = smem_u32(smem);

    int tid = threadIdx.x;
    int w = tid >> 5, lid = tid & 31;
    int bx = blockIdx.x;
    int bt = bx >> 3;                        // 0..15
    int js = bx & 7;
    int grp = bt;

    int j = js * 32 + w * 8 + (lid >> 2);
    int bcol[4];
#pragma unroll
    for (int r = 0; r < 4; r++) bcol[r] = (r >> 1) * 8 + (lid & 3) * 2 + (r & 1);

    // preload U slice (bf16 hi), rows r = w2*32 + type*8 + jl (shared by both dirs)
    for (int i = tid; i < 128 * 256; i += 128) {
        int r = i >> 8, k = i & 255;
        int w2 = r >> 5, type = (r >> 3) & 3, jl = r & 7;
        float u = U[(size_t)(type * 256 + js * 32 + w2 * 8 + jl) * DH + k];
        *(__nv_bfloat16*)(smem + SM_UHI + (r * AP + k) * 2) = __float2bfloat16(u);
    }

    int idx4 = lid >> 3, r8 = lid & 7;
    u32 aoff0 = (u32)(((w * 32 + (idx4 & 1) * 8 + r8) * AP + (idx4 >> 1) * 8) * 2);
    u32 aoff1 = aoff0 + (u32)(16 * AP * 2);
    u32 boff  = (u32)((((idx4 >> 1) * 8 + r8) * HP + (idx4 & 1) * 8) * 2);

    float c[2][4];
#pragma unroll
    for (int d = 0; d < 2; d++)
#pragma unroll
        for (int r = 0; r < 4; r++) c[d][r] = 0.f;
    __syncthreads();

    const u32 hsm_hi[2] = { SM_H0HI, SM_H1HI };
    const u32 hsm_lo[2] = { SM_H0LO, SM_H1LO };

    for (int t = 0; t < SS; t++) {
        int cur = t & 1, nxt = cur ^ 1;

#pragma unroll
        for (int d = 0; d < 2; d++) {
            int s = d ? (SS - 1 - t) : t;

            // EW prefetch for this dir (issued before wait; independent data)
            float4 e[4];
#pragma unroll
            for (int r = 0; r < 4; r++) {
                int wd = g_wordsT[s * BB + bt * BT + bcol[r]];
                e[r] = __ldg((const float4*)&g_EW[(size_t)wd * NGATE + j * 4]);
            }

            // wait for group's h(t) of dir d (released one full phase ago)
            if (t > 0) {
                if (tid < 8) {
                    unsigned* fp = &g_flags[d * 1024 + grp * 64 + tid * 8];
                    unsigned v;
                    do {
                        asm volatile("ld.acquire.gpu.u32 %0, [%1];"
                                     : "=r"(v) : "l"(fp) : "memory");
                    } while ((int)v < t);
                }
                __syncthreads();
            }

            // stage h(t)[dir d] 16 b x 256 k -> hi/lo bf16 tiles
            {
                const uint4* hb = (const uint4*)(g_hsplit +
                    ((size_t)(cur * 2 + d) * BB + bt * BT) * DH);
#pragma unroll
                for (int it = 0; it < 8; it++) {
                    int i = tid + it * 128;
                    int b = i >> 6, c4 = i & 63;
                    uint4 v = __ldcg(hb + b * 64 + c4);
                    u32 hi0 = __byte_perm(v.x, v.y, 0x5410);
                    u32 hi1 = __byte_perm(v.z, v.w, 0x5410);
                    u32 lo0 = __byte_perm(v.x, v.y, 0x7632);
                    u32 lo1 = __byte_perm(v.z, v.w, 0x7632);
                    int k0 = c4 * 4;
                    *(ull*)(smem + hsm_hi[d] + (b * HP + k0) * 2) = (ull)hi0 | ((ull)hi1 << 32);
                    *(ull*)(smem + hsm_lo[d] + (b * HP + k0) * 2) = (ull)lo0 | ((ull)lo1 << 32);
                }
            }
            __syncthreads();

            // fused 2-pass MMA: warp rows w*32..+31, 16 batch, K=256
            float acc[2][2][4];
#pragma unroll
            for (int mt = 0; mt < 2; mt++)
#pragma unroll
                for (int nt = 0; nt < 2; nt++)
#pragma unroll
                    for (int q = 0; q < 4; q++) acc[mt][nt][q] = 0.f;

#pragma unroll
            for (int kt = 0; kt < 16; kt++) {
                u32 koff = (u32)(kt * 32);
                u32 af0[4], af1[4], bh[4], bl[4];
                ldsm4(af0, sbase + SM_UHI + aoff0 + koff);
                ldsm4(af1, sbase + SM_UHI + aoff1 + koff);
                ldsm4(bh, sbase + hsm_hi[d] + boff + koff);
                ldsm4(bl, sbase + hsm_lo[d] + boff + koff);
                mma16816(acc[0][0], af0, bh + 0);
                mma16816(acc[0][1], af0, bh + 2);
                mma16816(acc[1][0], af1, bh + 0);
                mma16816(acc[1][1], af1, bh + 2);
                mma16816(acc[0][0], af0, bl + 0);
                mma16816(acc[0][1], af0, bl + 2);
                mma16816(acc[1][0], af1, bl + 0);
                mma16816(acc[1][1], af1, bl + 2);
            }

            // register epilogue: 4 cells (j, bcol[r])
            float hout[4];
#pragma unroll
            for (int r = 0; r < 4; r++) {
                int nt = r >> 1, q = r & 1;
                float gi = fsig (acc[0][nt][q]     + e[r].x);
                float gf = fsig (acc[0][nt][2 + q] + e[r].y);
                float go = fsig (acc[1][nt][q]     + e[r].z);
                float gc = ftanh(acc[1][nt][2 + q] + e[r].w);
                c[d][r] = gf * c[d][r] + gi * gc;
                hout[r] = go * ftanh(c[d][r]);
            }

            // pack h -> bf16 hi|lo u32, store to global [b][k=j]
            u32* hbuf = g_hsplit + (size_t)(nxt * 2 + d) * BB * DH + (size_t)bt * BT * DH + j;
#pragma unroll
            for (int r = 0; r < 4; r++) {
                u16 hi, lo;
                bsplit(hout[r], hi, lo);
                __stcg(hbuf + (size_t)bcol[r] * DH, (u32)hi | ((u32)lo << 16));
            }
            if (t == SS - 1) {
#pragma unroll
                for (int r = 0; r < 4; r++)
                    g_h[(size_t)d * DH * BB + (size_t)j * BB + bt * BT + bcol[r]] = hout[r];
            }

            __syncthreads();   // all h stores issued, all tile reads done
            if (t < SS - 1 && tid == 0) {
                asm volatile("st.release.gpu.u32 [%0], %1;"
                             :: "l"(&g_flags[d * 1024 + grp * 64 + js * 8]), "r"(t + 1)
                             : "memory");
            }
        }
    }
}

// ---------------- kernel 3: output layer ----------------
__global__ void out_kernel(const float* __restrict__ outW,
                           const float* __restrict__ outb,
                           float* __restrict__ pred) {
    int b = blockIdx.x;
    int tid = threadIdx.x;
    const float* hl = g_h;
    const float* hr = g_h + (size_t)DH * BB;
    float a0 = 0.f, a1 = 0.f;
    for (int idx = tid; idx < 512; idx += 128) {
        float v = (idx < 256) ? hl[idx * BB + b] : hr[(idx - 256) * BB + b];
        a0 += v * outW[idx];
        a1 += v * outW[512 + idx];
    }
#pragma unroll
    for (int o = 16; o > 0; o >>= 1) {
        a0 += __shfl_down_sync(0xFFFFFFFFu, a0, o);
        a1 += __shfl_down_sync(0xFFFFFFFFu, a1, o);
    }
    __shared__ float s0[4], s1[4];
    if ((tid & 31) == 0) { s0[tid >> 5] = a0; s1[tid >> 5] = a1; }
    __syncthreads();
    if (tid == 0) {
        pred[b * 2 + 0] = s0[0] + s0[1] + s0[2] + s0[3] + outb[0];
        pred[b * 2 + 1] = s1[0] + s1[1] + s1[2] + s1[3] + outb[1];
    }
}

// ---------------- launch ----------------
extern "C" void kernel_launch(void* const* d_in, const int* in_sizes, int n_in,
                              void* d_out, int out_size) {
    const int*   words = (const int*)d_in[0];
    const float* Emb   = (const float*)d_in[1];
    const float* W     = (const float*)d_in[2];
    const float* U     = (const float*)d_in[3];
    const float* bias  = (const float*)d_in[4];
    const float* outW  = (const float*)d_in[5];
    const float* outb  = (const float*)d_in[6];
    float* pred = (float*)d_out;

    cudaFuncSetAttribute(scan_kernel, cudaFuncAttributeMaxDynamicSharedMemorySize, SM_TOTAL);
    cudaFuncSetAttribute(ew_gemm2, cudaFuncAttributeMaxDynamicSharedMemorySize, EW_SMEM);

    reset_kernel<<<256, 256>>>(words);
    ew_gemm2<<<dim3((NDICT + 127) / 128, NGATE / 128), 256, EW_SMEM>>>(Emb, W, bias);
    scan_kernel<<<NBLK, 128, SM_TOTAL>>>(U);
    out_kernel<<<256, 128>>>(outW, outb, pred);
}

// round 10
// speedup vs baseline: 1.1674x; 1.1674x over previous
#include <cuda_runtime.h>
#include <cuda_bf16.h>
#include <cuda_fp16.h>
#include <cstdint>

typedef unsigned long long ull;
typedef unsigned int u32;
typedef unsigned short u16;

// ---------------- constants ----------------
#define NDICT   50000
#define DIN     256
#define DH      256
#define NGATE   1024
#define BB      256
#define SS      512
#define NBLK    128

// ---- scan smem (bytes); pitches conflict-free for ldmatrix
#define AP 264                      // U row pitch in fp16 (33 x 16B)
#define HP 264                      // h row pitch in fp16
#define SM_UH    0
#define SM_HT   (SM_UH + 128 * AP * 2)            // 67584
#define SM_TOTAL (SM_HT + 32 * HP * 2)            // 84480 B

// ---- ew_gemm2 smem (bytes); pitch 72 bf16 = 144 B
#define EP 72
#define EW_AH 0
#define EW_AL (EW_AH + 128 * EP * 2)
#define EW_BH (EW_AL + 128 * EP * 2)
#define EW_BL (EW_BH + 128 * EP * 2)
#define EW_BIAS (EW_BL + 128 * EP * 2)
#define EW_SMEM (EW_BIAS + 128 * 4)

// ---------------- device scratch ----------------
__device__ float g_EW[(size_t)NDICT * NGATE];  // Emb@W^T + bias, cols permuted j*4+type
__device__ u16   g_hfp16[2 * 2 * BB * DH];     // [buf][dir][b][k] h as fp16
__device__ float g_h[2 * DH * BB];             // final h [dir][j][b] fp32
__device__ int   g_wordsT[SS * BB];
__device__ unsigned g_flags[16 * 64];          // [group(dir,bt)][js*8]

// ---------------- helpers ----------------
__device__ __forceinline__ u32 smem_u32(const void* p) {
    u32 a; asm("{ .reg .u64 t; cvta.to.shared.u64 t, %1; cvt.u32.u64 %0, t; }"
               : "=r"(a) : "l"(p));
    return a;
}
__device__ __forceinline__ float fsig(float x) {
    float e = __expf(-x);
    return __fdividef(1.0f, 1.0f + e);
}
__device__ __forceinline__ float ftanh(float x) {
    float ax = fabsf(x);
    float e  = __expf(-2.0f * ax);
    float r  = __fdividef(1.0f - e, 1.0f + e);
    return copysignf(r, x);
}
__device__ __forceinline__ void ldsm4(u32* r, u32 addr) {
    asm volatile("ldmatrix.sync.aligned.m8n8.x4.shared.b16 {%0,%1,%2,%3}, [%4];"
                 : "=r"(r[0]), "=r"(r[1]), "=r"(r[2]), "=r"(r[3]) : "r"(addr));
}
// fp16 x fp16 -> fp32 accumulate
__device__ __forceinline__ void mma16816h(float* c, const u32* a, const u32* b) {
    asm volatile("mma.sync.aligned.m16n8k16.row.col.f32.f16.f16.f32 "
                 "{%0,%1,%2,%3}, {%4,%5,%6,%7}, {%8,%9}, {%0,%1,%2,%3};"
                 : "+f"(c[0]), "+f"(c[1]), "+f"(c[2]), "+f"(c[3])
                 : "r"(a[0]), "r"(a[1]), "r"(a[2]), "r"(a[3]), "r"(b[0]), "r"(b[1]));
}
// bf16 x bf16 -> fp32 accumulate (ew_gemm)
__device__ __forceinline__ void mma16816(float* c, const u32* a, const u32* b) {
    asm volatile("mma.sync.aligned.m16n8k16.row.col.f32.bf16.bf16.f32 "
                 "{%0,%1,%2,%3}, {%4,%5,%6,%7}, {%8,%9}, {%0,%1,%2,%3};"
                 : "+f"(c[0]), "+f"(c[1]), "+f"(c[2]), "+f"(c[3])
                 : "r"(a[0]), "r"(a[1]), "r"(a[2]), "r"(a[3]), "r"(b[0]), "r"(b[1]));
}
__device__ __forceinline__ void bsplit(float x, u16& hi, u16& lo) {
    __nv_bfloat16 h = __float2bfloat16(x);
    __nv_bfloat16 l = __float2bfloat16(x - __bfloat162float(h));
    hi = __bfloat16_as_ushort(h);
    lo = __bfloat16_as_ushort(l);
}

// ---------------- kernel 0: reset ----------------
__global__ void reset_kernel(const int* __restrict__ words) {
    int idx = blockIdx.x * blockDim.x + threadIdx.x;
    if (idx < 16 * 64) g_flags[idx] = 0u;
    // zero h buffer 0 (both dirs) = first 2*BB*DH u16 = BB*DH u32
    u32* hz = (u32*)g_hfp16;
    for (int i = idx; i < BB * DH; i += gridDim.x * blockDim.x) hz[i] = 0u;
    for (int i = idx; i < SS * BB; i += gridDim.x * blockDim.x) {
        int s = i >> 8, b = i & 255;
        g_wordsT[i] = words[b * SS + s];
    }
}

// ---------------- kernel 1: EW = Emb @ W^T (+bias), split-bf16 HMMA ----------------
__global__ __launch_bounds__(256) void ew_gemm2(const float* __restrict__ Emb,
                                                const float* __restrict__ W,
                                                const float* __restrict__ bias) {
    extern __shared__ __align__(16) char esm[];
    u32 sb = smem_u32(esm);
    float* biasp = (float*)(esm + EW_BIAS);

    int tid = threadIdx.x;
    int w = tid >> 5, lid = tid & 31;
    int mbase = blockIdx.x * 128;
    int nbase = blockIdx.y * 128;
    int wm = (w & 3) * 32, wn = (w >> 2) * 64;

    if (tid < 128) {
        int colp = nbase + tid;
        biasp[tid] = bias[(colp & 3) * 256 + (colp >> 2)];
    }

    int idx4 = lid >> 3, r8 = lid & 7;
    u32 aoff0 = (u32)(((wm + (idx4 & 1) * 8 + r8) * EP + (idx4 >> 1) * 8) * 2);
    u32 aoff1 = aoff0 + (u32)(16 * EP * 2);
    u32 boffB = (u32)(((wn + (idx4 >> 1) * 8 + r8) * EP + (idx4 & 1) * 8) * 2);

    float acc[2][8][4];
#pragma unroll
    for (int mt = 0; mt < 2; mt++)
#pragma unroll
        for (int n8 = 0; n8 < 8; n8++)
#pragma unroll
            for (int q = 0; q < 4; q++) acc[mt][n8][q] = 0.f;

    for (int kb = 0; kb < 4; kb++) {
        int k0 = kb * 64;
        for (int i = tid; i < 128 * 16; i += 256) {
            int row = i >> 4, kq = (i & 15) * 4;
            int va = mbase + row;
            float4 v = make_float4(0.f, 0.f, 0.f, 0.f);
            if (va < NDICT) v = *(const float4*)&Emb[(size_t)va * DIN + k0 + kq];
            u16 h0, l0, h1, l1, h2, l2, h3, l3;
            bsplit(v.x, h0, l0); bsplit(v.y, h1, l1);
            bsplit(v.z, h2, l2); bsplit(v.w, h3, l3);
            u32* ah = (u32*)(esm + EW_AH + (row * EP + kq) * 2);
            u32* al = (u32*)(esm + EW_AL + (row * EP + kq) * 2);
            ah[0] = (u32)h0 | ((u32)h1 << 16); ah[1] = (u32)h2 | ((u32)h3 << 16);
            al[0] = (u32)l0 | ((u32)l1 << 16); al[1] = (u32)l2 | ((u32)l3 << 16);
        }
        for (int i = tid; i < 128 * 16; i += 256) {
            int row = i >> 4, kq = (i & 15) * 4;
            int colp = nbase + row;
            int grow = (colp & 3) * 256 + (colp >> 2);
            float4 v = *(const float4*)&W[(size_t)grow * DIN + k0 + kq];
            u16 h0, l0, h1, l1, h2, l2, h3, l3;
            bsplit(v.x, h0, l0); bsplit(v.y, h1, l1);
            bsplit(v.z, h2, l2); bsplit(v.w, h3, l3);
            u32* bh = (u32*)(esm + EW_BH + (row * EP + kq) * 2);
            u32* bl = (u32*)(esm + EW_BL + (row * EP + kq) * 2);
            bh[0] = (u32)h0 | ((u32)h1 << 16); bh[1] = (u32)h2 | ((u32)h3 << 16);
            bl[0] = (u32)l0 | ((u32)l1 << 16); bl[1] = (u32)l2 | ((u32)l3 << 16);
        }
        __syncthreads();

#pragma unroll
        for (int kt = 0; kt < 4; kt++) {
            u32 koff = (u32)(kt * 32);
            u32 a0h[4], a1h[4], a0l[4], a1l[4];
            ldsm4(a0h, sb + EW_AH + aoff0 + koff);
            ldsm4(a1h, sb + EW_AH + aoff1 + koff);
            ldsm4(a0l, sb + EW_AL + aoff0 + koff);
            ldsm4(a1l, sb + EW_AL + aoff1 + koff);
#pragma unroll
            for (int p = 0; p < 4; p++) {
                u32 po = (u32)(p * 16 * EP * 2);
                u32 bh[4], bl[4];
                ldsm4(bh, sb + EW_BH + boffB + po + koff);
                ldsm4(bl, sb + EW_BL + boffB + po + koff);
                mma16816(acc[0][2 * p + 0], a0h, bh + 0);
                mma16816(acc[0][2 * p + 1], a0h, bh + 2);
                mma16816(acc[1][2 * p + 0], a1h, bh + 0);
                mma16816(acc[1][2 * p + 1], a1h, bh + 2);
                mma16816(acc[0][2 * p + 0], a0h, bl + 0);
                mma16816(acc[0][2 * p + 1], a0h, bl + 2);
                mma16816(acc[1][2 * p + 0], a1h, bl + 0);
                mma16816(acc[1][2 * p + 1], a1h, bl + 2);
                mma16816(acc[0][2 * p + 0], a0l, bh + 0);
                mma16816(acc[0][2 * p + 1], a0l, bh + 2);
                mma16816(acc[1][2 * p + 0], a1l, bh + 0);
                mma16816(acc[1][2 * p + 1], a1l, bh + 2);
            }
        }
        __syncthreads();
    }

#pragma unroll
    for (int mt = 0; mt < 2; mt++) {
#pragma unroll
        for (int n8 = 0; n8 < 8; n8++) {
            int nl = wn + n8 * 8 + (lid & 3) * 2;
            int col = nbase + nl;
            float b0 = biasp[nl], b1 = biasp[nl + 1];
            int r0 = mbase + wm + mt * 16 + (lid >> 2);
            if (r0 < NDICT)
                *(float2*)&g_EW[(size_t)r0 * NGATE + col] =
                    make_float2(acc[mt][n8][0] + b0, acc[mt][n8][1] + b1);
            if (r0 + 8 < NDICT)
                *(float2*)&g_EW[(size_t)(r0 + 8) * NGATE + col] =
                    make_float2(acc[mt][n8][2] + b0, acc[mt][n8][3] + b1);
        }
    }
}

// ---------------- kernel 2: persistent scan — fp16 single-pass HMMA ----------------
// grid = 128 CTAs: dir(2) x batch-tile(8, 32 rows) x gate-slice(8, 32 j)
// Warp-tile rows r = w*32 + type*8 + jl -> each thread owns all 4 gates of one j
__global__ __launch_bounds__(128, 1) void scan_kernel(const float* __restrict__ U) {
    extern __shared__ __align__(16) char smem[];
    u32 sbase = smem_u32(smem);

    int tid = threadIdx.x;
    int w = tid >> 5, lid = tid & 31;
    int bx = blockIdx.x;
    int dir = bx >> 6;
    int bt  = (bx >> 3) & 7;
    int js  = bx & 7;
    int grp = bx >> 3;

    int j = js * 32 + w * 8 + (lid >> 2);   // this thread's hidden unit
    int bcol[8];
#pragma unroll
    for (int r = 0; r < 8; r++) bcol[r] = (r >> 1) * 8 + (lid & 3) * 2 + (r & 1);

    // preload U slice (fp16), rows r = w2*32 + type*8 + jl
    for (int i = tid; i < 128 * 256; i += 128) {
        int r = i >> 8, k = i & 255;
        int w2 = r >> 5, type = (r >> 3) & 3, jl = r & 7;
        float u = U[(size_t)(type * 256 + js * 32 + w2 * 8 + jl) * DH + k];
        *(__half*)(smem + SM_UH + (r * AP + k) * 2) = __float2half_rn(u);
    }

    int idx4 = lid >> 3, r8 = lid & 7;
    u32 aoff0 = (u32)(((w * 32 + (idx4 & 1) * 8 + r8) * AP + (idx4 >> 1) * 8) * 2);
    u32 aoff1 = aoff0 + (u32)(16 * AP * 2);
    u32 boff0 = (u32)((((idx4 >> 1) * 8 + r8) * HP + (idx4 & 1) * 8) * 2);
    u32 boff1 = boff0 + (u32)(16 * HP * 2);

    float c[8];
#pragma unroll
    for (int r = 0; r < 8; r++) c[r] = 0.f;
    __syncthreads();

    for (int t = 0; t < SS; t++) {
        int cur = t & 1, nxt = cur ^ 1;
        int s = dir ? (SS - 1 - t) : t;

        // EW prefetch: e[r] = [i,f,o,c] inputs for (j, bcol[r])
        float4 e[8];
#pragma unroll
        for (int r = 0; r < 8; r++) {
            int wd = g_wordsT[s * BB + bt * 32 + bcol[r]];
            e[r] = __ldg((const float4*)&g_EW[(size_t)wd * NGATE + j * 4]);
        }

        // stage h(t) [32 b x 256 k] fp16 -> smem, pitch HP (raw 16B copies)
        {
            const uint4* hb = (const uint4*)(g_hfp16 +
                ((size_t)(cur * 2 + dir) * BB + bt * 32) * DH);
#pragma unroll
            for (int it = 0; it < 8; it++) {
                int i = tid + it * 128;
                int b = i >> 5, c8 = i & 31;          // c8: uint4 index (8 k each)
                uint4 v = __ldcg(hb + b * 32 + c8);
                *(uint4*)(smem + SM_HT + (b * HP + c8 * 8) * 2) = v;
            }
        }
        __syncthreads();

        // single-pass fp16 MMA: warp rows w*32..+31 (8 j x 4 types), 32 batch, K=256
        float acc[2][4][4];
#pragma unroll
        for (int mt = 0; mt < 2; mt++)
#pragma unroll
            for (int nt = 0; nt < 4; nt++)
#pragma unroll
                for (int q = 0; q < 4; q++) acc[mt][nt][q] = 0.f;

#pragma unroll
        for (int kt = 0; kt < 16; kt++) {
            u32 koff = (u32)(kt * 32);
            u32 af0[4], af1[4], bh[8];
            ldsm4(af0, sbase + SM_UH + aoff0 + koff);
            ldsm4(af1, sbase + SM_UH + aoff1 + koff);
            ldsm4(bh,     sbase + SM_HT + boff0 + koff);
            ldsm4(bh + 4, sbase + SM_HT + boff1 + koff);
            mma16816h(acc[0][0], af0, bh + 0);
            mma16816h(acc[0][1], af0, bh + 2);
            mma16816h(acc[0][2], af0, bh + 4);
            mma16816h(acc[0][3], af0, bh + 6);
            mma16816h(acc[1][0], af1, bh + 0);
            mma16816h(acc[1][1], af1, bh + 2);
            mma16816h(acc[1][2], af1, bh + 4);
            mma16816h(acc[1][3], af1, bh + 6);
        }

        // register epilogue: rows lid/4 + {0,8,16,24} = types {i,f,o,c} of unit j
        float hout[8];
#pragma unroll
        for (int r = 0; r < 8; r++) {
            int nt = r >> 1, q = r & 1;
            float gi = fsig (acc[0][nt][q]     + e[r].x);
            float gf = fsig (acc[0][nt][2 + q] + e[r].y);
            float go = fsig (acc[1][nt][q]     + e[r].z);
            float gc = ftanh(acc[1][nt][2 + q] + e[r].w);
            c[r] = gf * c[r] + gi * gc;
            hout[r] = go * ftanh(c[r]);
        }

        // store h as fp16 to global [b][k=j]
        u16* hbuf = g_hfp16 + (size_t)(nxt * 2 + dir) * BB * DH + (size_t)bt * 32 * DH + j;
#pragma unroll
        for (int r = 0; r < 8; r++) {
            __half hv = __float2half_rn(hout[r]);
            __stcg((__half*)(hbuf + (size_t)bcol[r] * DH), hv);
        }
        if (t == SS - 1) {
#pragma unroll
            for (int r = 0; r < 8; r++)
                g_h[(size_t)dir * DH * BB + (size_t)j * BB + bt * 32 + bcol[r]] = hout[r];
        }

        __syncthreads();   // tile reads done, h stores issued
        if (t < SS - 1) {
            if (tid == 0) {
                asm volatile("st.release.gpu.u32 [%0], %1;"
                             :: "l"(&g_flags[grp * 64 + js * 8]), "r"(t + 1) : "memory");
            }
            if (tid < 8) {
                unsigned* fp = &g_flags[grp * 64 + tid * 8];
                unsigned v;
                do {
                    asm volatile("ld.acquire.gpu.u32 %0, [%1];"
                                 : "=r"(v) : "l"(fp) : "memory");
                } while ((int)v < t + 1);
            }
            __syncthreads();
        }
    }
}

// ---------------- kernel 3: output layer ----------------
__global__ void out_kernel(const float* __restrict__ outW,
                           const float* __restrict__ outb,
                           float* __restrict__ pred) {
    int b = blockIdx.x;
    int tid = threadIdx.x;
    const float* hl = g_h;
    const float* hr = g_h + (size_t)DH * BB;
    float a0 = 0.f, a1 = 0.f;
    for (int idx = tid; idx < 512; idx += 128) {
        float v = (idx < 256) ? hl[idx * BB + b] : hr[(idx - 256) * BB + b];
        a0 += v * outW[idx];
        a1 += v * outW[512 + idx];
    }
#pragma unroll
    for (int o = 16; o > 0; o >>= 1) {
        a0 += __shfl_down_sync(0xFFFFFFFFu, a0, o);
        a1 += __shfl_down_sync(0xFFFFFFFFu, a1, o);
    }
    __shared__ float s0[4], s1[4];
    if ((tid & 31) == 0) { s0[tid >> 5] = a0; s1[tid >> 5] = a1; }
    __syncthreads();
    if (tid == 0) {
        pred[b * 2 + 0] = s0[0] + s0[1] + s0[2] + s0[3] + outb[0];
        pred[b * 2 + 1] = s1[0] + s1[1] + s1[2] + s1[3] + outb[1];
    }
}

// ---------------- launch ----------------
extern "C" void kernel_launch(void* const* d_in, const int* in_sizes, int n_in,
                              void* d_out, int out_size) {
    const int*   words = (const int*)d_in[0];
    const float* Emb   = (const float*)d_in[1];
    const float* W     = (const float*)d_in[2];
    const float* U     = (const float*)d_in[3];
    const float* bias  = (const float*)d_in[4];
    const float* outW  = (const float*)d_in[5];
    const float* outb  = (const float*)d_in[6];
    float* pred = (float*)d_out;

    cudaFuncSetAttribute(scan_kernel, cudaFuncAttributeMaxDynamicSharedMemorySize, SM_TOTAL);
    cudaFuncSetAttribute(ew_gemm2, cudaFuncAttributeMaxDynamicSharedMemorySize, EW_SMEM);

    reset_kernel<<<256, 256>>>(words);
    ew_gemm2<<<dim3((NDICT + 127) / 128, NGATE / 128), 256, EW_SMEM>>>(Emb, W, bias);
    scan_kernel<<<NBLK, 128, SM_TOTAL>>>(U);
    out_kernel<<<256, 128>>>(outW, outb, pred);
}

// round 12
// speedup vs baseline: 1.4212x; 1.2174x over previous
#include <cuda_runtime.h>
#include <cuda_bf16.h>
#include <cuda_fp16.h>
#include <cstdint>

typedef unsigned long long ull;
typedef unsigned int u32;
typedef unsigned short u16;

// ---------------- constants ----------------
#define NDICT   50000
#define DIN     256
#define DH      256
#define NGATE   1024
#define BB      256
#define SS      512
#define NBLK    128

// ---- scan smem (bytes); pitches conflict-free for ldmatrix
#define AP 264                      // U row pitch in fp16 (33 x 16B)
#define HP 264                      // h row pitch in fp16
#define SM_UH    0
#define SM_HT   (SM_UH + 128 * AP * 2)            // 67584
#define SM_TOTAL (SM_HT + 32 * HP * 2)            // 84480 B

// ---- ew_gemm2 smem (bytes); pitch 72 bf16 = 144 B
#define EP 72
#define EW_AH 0
#define EW_AL (EW_AH + 128 * EP * 2)
#define EW_BH (EW_AL + 128 * EP * 2)
#define EW_BL (EW_BH + 128 * EP * 2)
#define EW_BIAS (EW_BL + 128 * EP * 2)
#define EW_SMEM (EW_BIAS + 128 * 4)

// ---------------- device scratch ----------------
__device__ float g_EW[(size_t)NDICT * NGATE];  // Emb@W^T + bias, cols permuted j*4+type
__device__ u16   g_hfp16[2 * 2 * BB * DH];     // [buf][dir][b][k] h as fp16
__device__ float g_h[2 * DH * BB];             // final h [dir][j][b] fp32
__device__ int   g_wordsT[SS * BB];
__device__ unsigned g_flags[16 * 64];          // [group(dir,bt)][js*8]

// ---------------- helpers ----------------
__device__ __forceinline__ u32 smem_u32(const void* p) {
    u32 a; asm("{ .reg .u64 t; cvta.to.shared.u64 t, %1; cvt.u32.u64 %0, t; }"
               : "=r"(a) : "l"(p));
    return a;
}
__device__ __forceinline__ float fsig(float x) {
    float e = __expf(-x);
    return __fdividef(1.0f, 1.0f + e);
}
__device__ __forceinline__ float ftanh(float x) {
    float ax = fabsf(x);
    float e  = __expf(-2.0f * ax);
    float r  = __fdividef(1.0f - e, 1.0f + e);
    return copysignf(r, x);
}
__device__ __forceinline__ void ldsm4(u32* r, u32 addr) {
    asm volatile("ldmatrix.sync.aligned.m8n8.x4.shared.b16 {%0,%1,%2,%3}, [%4];"
                 : "=r"(r[0]), "=r"(r[1]), "=r"(r[2]), "=r"(r[3]) : "r"(addr));
}
// fp16 x fp16 -> fp32 accumulate
__device__ __forceinline__ void mma16816h(float* c, const u32* a, const u32* b) {
    asm volatile("mma.sync.aligned.m16n8k16.row.col.f32.f16.f16.f32 "
                 "{%0,%1,%2,%3}, {%4,%5,%6,%7}, {%8,%9}, {%0,%1,%2,%3};"
                 : "+f"(c[0]), "+f"(c[1]), "+f"(c[2]), "+f"(c[3])
                 : "r"(a[0]), "r"(a[1]), "r"(a[2]), "r"(a[3]), "r"(b[0]), "r"(b[1]));
}
// bf16 x bf16 -> fp32 accumulate (ew_gemm)
__device__ __forceinline__ void mma16816(float* c, const u32* a, const u32* b) {
    asm volatile("mma.sync.aligned.m16n8k16.row.col.f32.bf16.bf16.f32 "
                 "{%0,%1,%2,%3}, {%4,%5,%6,%7}, {%8,%9}, {%0,%1,%2,%3};"
                 : "+f"(c[0]), "+f"(c[1]), "+f"(c[2]), "+f"(c[3])
                 : "r"(a[0]), "r"(a[1]), "r"(a[2]), "r"(a[3]), "r"(b[0]), "r"(b[1]));
}
__device__ __forceinline__ void bsplit(float x, u16& hi, u16& lo) {
    __nv_bfloat16 h = __float2bfloat16(x);
    __nv_bfloat16 l = __float2bfloat16(x - __bfloat162float(h));
    hi = __bfloat16_as_ushort(h);
    lo = __bfloat16_as_ushort(l);
}

// ---------------- kernel 0: reset ----------------
__global__ void reset_kernel(const int* __restrict__ words) {
    int idx = blockIdx.x * blockDim.x + threadIdx.x;
    if (idx < 16 * 64) g_flags[idx] = 0u;
    u32* hz = (u32*)g_hfp16;
    for (int i = idx; i < BB * DH; i += gridDim.x * blockDim.x) hz[i] = 0u;
    for (int i = idx; i < SS * BB; i += gridDim.x * blockDim.x) {
        int s = i >> 8, b = i & 255;
        g_wordsT[i] = words[b * SS + s];
    }
}

// ---------------- kernel 1: EW = Emb @ W^T (+bias), split-bf16 HMMA ----------------
__global__ __launch_bounds__(256) void ew_gemm2(const float* __restrict__ Emb,
                                                const float* __restrict__ W,
                                                const float* __restrict__ bias) {
    extern __shared__ __align__(16) char esm[];
    u32 sb = smem_u32(esm);
    float* biasp = (float*)(esm + EW_BIAS);

    int tid = threadIdx.x;
    int w = tid >> 5, lid = tid & 31;
    int mbase = blockIdx.x * 128;
    int nbase = blockIdx.y * 128;
    int wm = (w & 3) * 32, wn = (w >> 2) * 64;

    if (tid < 128) {
        int colp = nbase + tid;
        biasp[tid] = bias[(colp & 3) * 256 + (colp >> 2)];
    }

    int idx4 = lid >> 3, r8 = lid & 7;
    u32 aoff0 = (u32)(((wm + (idx4 & 1) * 8 + r8) * EP + (idx4 >> 1) * 8) * 2);
    u32 aoff1 = aoff0 + (u32)(16 * EP * 2);
    u32 boffB = (u32)(((wn + (idx4 >> 1) * 8 + r8) * EP + (idx4 & 1) * 8) * 2);

    float acc[2][8][4];
#pragma unroll
    for (int mt = 0; mt < 2; mt++)
#pragma unroll
        for (int n8 = 0; n8 < 8; n8++)
#pragma unroll
            for (int q = 0; q < 4; q++) acc[mt][n8][q] = 0.f;

    for (int kb = 0; kb < 4; kb++) {
        int k0 = kb * 64;
        for (int i = tid; i < 128 * 16; i += 256) {
            int row = i >> 4, kq = (i & 15) * 4;
            int va = mbase + row;
            float4 v = make_float4(0.f, 0.f, 0.f, 0.f);
            if (va < NDICT) v = *(const float4*)&Emb[(size_t)va * DIN + k0 + kq];
            u16 h0, l0, h1, l1, h2, l2, h3, l3;
            bsplit(v.x, h0, l0); bsplit(v.y, h1, l1);
            bsplit(v.z, h2, l2); bsplit(v.w, h3, l3);
            u32* ah = (u32*)(esm + EW_AH + (row * EP + kq) * 2);
            u32* al = (u32*)(esm + EW_AL + (row * EP + kq) * 2);
            ah[0] = (u32)h0 | ((u32)h1 << 16); ah[1] = (u32)h2 | ((u32)h3 << 16);
            al[0] = (u32)l0 | ((u32)l1 << 16); al[1] = (u32)l2 | ((u32)l3 << 16);
        }
        for (int i = tid; i < 128 * 16; i += 256) {
            int row = i >> 4, kq = (i & 15) * 4;
            int colp = nbase + row;
            int grow = (colp & 3) * 256 + (colp >> 2);
            float4 v = *(const float4*)&W[(size_t)grow * DIN + k0 + kq];
            u16 h0, l0, h1, l1, h2, l2, h3, l3;
            bsplit(v.x, h0, l0); bsplit(v.y, h1, l1);
            bsplit(v.z, h2, l2); bsplit(v.w, h3, l3);
            u32* bh = (u32*)(esm + EW_BH + (row * EP + kq) * 2);
            u32* bl = (u32*)(esm + EW_BL + (row * EP + kq) * 2);
            bh[0] = (u32)h0 | ((u32)h1 << 16); bh[1] = (u32)h2 | ((u32)h3 << 16);
            bl[0] = (u32)l0 | ((u32)l1 << 16); bl[1] = (u32)l2 | ((u32)l3 << 16);
        }
        __syncthreads();

#pragma unroll
        for (int kt = 0; kt < 4; kt++) {
            u32 koff = (u32)(kt * 32);
            u32 a0h[4], a1h[4], a0l[4], a1l[4];
            ldsm4(a0h, sb + EW_AH + aoff0 + koff);
            ldsm4(a1h, sb + EW_AH + aoff1 + koff);
            ldsm4(a0l, sb + EW_AL + aoff0 + koff);
            ldsm4(a1l, sb + EW_AL + aoff1 + koff);
#pragma unroll
            for (int p = 0; p < 4; p++) {
                u32 po = (u32)(p * 16 * EP * 2);
                u32 bh[4], bl[4];
                ldsm4(bh, sb + EW_BH + boffB + po + koff);
                ldsm4(bl, sb + EW_BL + boffB + po + koff);
                mma16816(acc[0][2 * p + 0], a0h, bh + 0);
                mma16816(acc[0][2 * p + 1], a0h, bh + 2);
                mma16816(acc[1][2 * p + 0], a1h, bh + 0);
                mma16816(acc[1][2 * p + 1], a1h, bh + 2);
                mma16816(acc[0][2 * p + 0], a0h, bl + 0);
                mma16816(acc[0][2 * p + 1], a0h, bl + 2);
                mma16816(acc[1][2 * p + 0], a1h, bl + 0);
                mma16816(acc[1][2 * p + 1], a1h, bl + 2);
                mma16816(acc[0][2 * p + 0], a0l, bh + 0);
                mma16816(acc[0][2 * p + 1], a0l, bh + 2);
                mma16816(acc[1][2 * p + 0], a1l, bh + 0);
                mma16816(acc[1][2 * p + 1], a1l, bh + 2);
            }
        }
        __syncthreads();
    }

#pragma unroll
    for (int mt = 0; mt < 2; mt++) {
#pragma unroll
        for (int n8 = 0; n8 < 8; n8++) {
            int nl = wn + n8 * 8 + (lid & 3) * 2;
            int col = nbase + nl;
            float b0 = biasp[nl], b1 = biasp[nl + 1];
            int r0 = mbase + wm + mt * 16 + (lid >> 2);
            if (r0 < NDICT)
                *(float2*)&g_EW[(size_t)r0 * NGATE + col] =
                    make_float2(acc[mt][n8][0] + b0, acc[mt][n8][1] + b1);
            if (r0 + 8 < NDICT)
                *(float2*)&g_EW[(size_t)(r0 + 8) * NGATE + col] =
                    make_float2(acc[mt][n8][2] + b0, acc[mt][n8][3] + b1);
        }
    }
}

// ---------------- kernel 2: persistent scan — fp16 HMMA, pipelined step ----------------
// grid = 128 CTAs: dir(2) x batch-tile(8, 32 rows) x gate-slice(8, 32 j)
// Per step: stage k-half0 | [issue k-half1] MMA half0 | MMA half1 | reg epilogue
__global__ __launch_bounds__(128, 1) void scan_kernel(const float* __restrict__ U) {
    extern __shared__ __align__(16) char smem[];
    u32 sbase = smem_u32(smem);

    int tid = threadIdx.x;
    int w = tid >> 5, lid = tid & 31;
    int bx = blockIdx.x;
    int dir = bx >> 6;
    int bt  = (bx >> 3) & 7;
    int js  = bx & 7;
    int grp = bx >> 3;

    int j = js * 32 + w * 8 + (lid >> 2);   // this thread's hidden unit
    int bcol[8];
#pragma unroll
    for (int r = 0; r < 8; r++) bcol[r] = (r >> 1) * 8 + (lid & 3) * 2 + (r & 1);

    // preload U slice (fp16), rows r = w2*32 + type*8 + jl
    for (int i = tid; i < 128 * 256; i += 128) {
        int r = i >> 8, k = i & 255;
        int w2 = r >> 5, type = (r >> 3) & 3, jl = r & 7;
        float u = U[(size_t)(type * 256 + js * 32 + w2 * 8 + jl) * DH + k];
        *(__half*)(smem + SM_UH + (r * AP + k) * 2) = __float2half_rn(u);
    }

    int idx4 = lid >> 3, r8 = lid & 7;
    u32 aoff0 = (u32)(((w * 32 + (idx4 & 1) * 8 + r8) * AP + (idx4 >> 1) * 8) * 2);
    u32 aoff1 = aoff0 + (u32)(16 * AP * 2);
    u32 boff0 = (u32)((((idx4 >> 1) * 8 + r8) * HP + (idx4 & 1) * 8) * 2);
    u32 boff1 = boff0 + (u32)(16 * HP * 2);

    float c[8];
#pragma unroll
    for (int r = 0; r < 8; r++) c[r] = 0.f;

    // EW prefetch for t=0
    float4 e[8];
    {
        int s0 = dir ? (SS - 1) : 0;
#pragma unroll
        for (int r = 0; r < 8; r++) {
            int wd = g_wordsT[s0 * BB + bt * 32 + bcol[r]];
            e[r] = __ldg((const float4*)&g_EW[(size_t)wd * NGATE + j * 4]);
        }
    }
    __syncthreads();

    for (int t = 0; t < SS; t++) {
        int cur = t & 1, nxt = cur ^ 1;

        const uint4* hb = (const uint4*)(g_hfp16 +
            ((size_t)(cur * 2 + dir) * BB + bt * 32) * DH);

        // ---- stage k-half 0 (k 0..127)
#pragma unroll
        for (int it = 0; it < 4; it++) {
            int i = tid + it * 128;
            int b = i >> 4, c8 = i & 15;
            uint4 v = __ldcg(hb + b * 32 + c8);
            *(uint4*)(smem + SM_HT + (b * HP + c8 * 8) * 2) = v;
        }
        __syncthreads();

        // ---- issue k-half 1 loads+stores (in flight during MMA half 0)
#pragma unroll
        for (int it = 0; it < 4; it++) {
            int i = tid + it * 128;
            int b = i >> 4, c8 = (i & 15) + 16;
            uint4 v = __ldcg(hb + b * 32 + c8);
            *(uint4*)(smem + SM_HT + (b * HP + c8 * 8) * 2) = v;
        }

        float acc[2][4][4];
#pragma unroll
        for (int mt = 0; mt < 2; mt++)
#pragma unroll
            for (int nt = 0; nt < 4; nt++)
#pragma unroll
                for (int q = 0; q < 4; q++) acc[mt][nt][q] = 0.f;

        // ---- MMA k-half 0 (kt 0..7)
#pragma unroll
        for (int kt = 0; kt < 8; kt++) {
            u32 koff = (u32)(kt * 32);
            u32 af0[4], af1[4], bh[8];
            ldsm4(af0, sbase + SM_UH + aoff0 + koff);
            ldsm4(af1, sbase + SM_UH + aoff1 + koff);
            ldsm4(bh,     sbase + SM_HT + boff0 + koff);
            ldsm4(bh + 4, sbase + SM_HT + boff1 + koff);
            mma16816h(acc[0][0], af0, bh + 0);
            mma16816h(acc[0][1], af0, bh + 2);
            mma16816h(acc[0][2], af0, bh + 4);
            mma16816h(acc[0][3], af0, bh + 6);
            mma16816h(acc[1][0], af1, bh + 0);
            mma16816h(acc[1][1], af1, bh + 2);
            mma16816h(acc[1][2], af1, bh + 4);
            mma16816h(acc[1][3], af1, bh + 6);
        }
        __syncthreads();   // half-1 STS drained

        // ---- MMA k-half 1 (kt 8..15)
#pragma unroll
        for (int kt = 8; kt < 16; kt++) {
            u32 koff = (u32)(kt * 32);
            u32 af0[4], af1[4], bh[8];
            ldsm4(af0, sbase + SM_UH + aoff0 + koff);
            ldsm4(af1, sbase + SM_UH + aoff1 + koff);
            ldsm4(bh,     sbase + SM_HT + boff0 + koff);
            ldsm4(bh + 4, sbase + SM_HT + boff1 + koff);
            mma16816h(acc[0][0], af0, bh + 0);
            mma16816h(acc[0][1], af0, bh + 2);
            mma16816h(acc[0][2], af0, bh + 4);
            mma16816h(acc[0][3], af0, bh + 6);
            mma16816h(acc[1][0], af1, bh + 0);
            mma16816h(acc[1][1], af1, bh + 2);
            mma16816h(acc[1][2], af1, bh + 4);
            mma16816h(acc[1][3], af1, bh + 6);
        }

        // ---- register epilogue
        float hout[8];
#pragma unroll
        for (int r = 0; r < 8; r++) {
            int nt = r >> 1, q = r & 1;
            float gi = fsig (acc[0][nt][q]     + e[r].x);
            float gf = fsig (acc[0][nt][2 + q] + e[r].y);
            float go = fsig (acc[1][nt][q]     + e[r].z);
            float gc = ftanh(acc[1][nt][2 + q] + e[r].w);
            c[r] = gf * c[r] + gi * gc;
            hout[r] = go * ftanh(c[r]);
        }

        // store h as fp16 to global [b][k=j]
        u16* hbuf = g_hfp16 + (size_t)(nxt * 2 + dir) * BB * DH + (size_t)bt * 32 * DH + j;
#pragma unroll
        for (int r = 0; r < 8; r++) {
            __half hv = __float2half_rn(hout[r]);
            __stcg((__half*)(hbuf + (size_t)bcol[r] * DH), hv);
        }
        if (t == SS - 1) {
#pragma unroll
            for (int r = 0; r < 8; r++)
                g_h[(size_t)dir * DH * BB + (size_t)j * BB + bt * 32 + bcol[r]] = hout[r];
        }

        __syncthreads();   // all tile reads done, all h stores issued
        if (t < SS - 1) {
            if (tid == 0) {
                asm volatile("st.release.gpu.u32 [%0], %1;"
                             :: "l"(&g_flags[grp * 64 + js * 8]), "r"(t + 1) : "memory");
            }
            // EW prefetch for t+1 — LDGs in flight during the poll
            {
                int sn = dir ? (SS - 2 - t) : (t + 1);
#pragma unroll
                for (int r = 0; r < 8; r++) {
                    int wd = g_wordsT[sn * BB + bt * 32 + bcol[r]];
                    e[r] = __ldg((const float4*)&g_EW[(size_t)wd * NGATE + j * 4]);
                }
            }
            // warp 0 polls the group's 8 flags
            if (tid < 32) {
                unsigned* fp = &g_flags[grp * 64 + (lid & 7) * 8];
                unsigned v;
                do {
                    asm volatile("ld.acquire.gpu.u32 %0, [%1];"
                                 : "=r"(v) : "l"(fp) : "memory");
                } while ((int)v < t + 1);
            }
            __syncthreads();
        }
    }
}

// ---------------- kernel 3: output layer ----------------
__global__ void out_kernel(const float* __restrict__ outW,
                           const float* __restrict__ outb,
                           float* __restrict__ pred) {
    int b = blockIdx.x;
    int tid = threadIdx.x;
    const float* hl = g_h;
    const float* hr = g_h + (size_t)DH * BB;
    float a0 = 0.f, a1 = 0.f;
    for (int idx = tid; idx < 512; idx += 128) {
        float v = (idx < 256) ? hl[idx * BB + b] : hr[(idx - 256) * BB + b];
        a0 += v * outW[idx];
        a1 += v * outW[512 + idx];
    }
#pragma unroll
    for (int o = 16; o > 0; o >>= 1) {
        a0 += __shfl_down_sync(0xFFFFFFFFu, a0, o);
        a1 += __shfl_down_sync(0xFFFFFFFFu, a1, o);
    }
    __shared__ float s0[4], s1[4];
    if ((tid & 31) == 0) { s0[tid >> 5] = a0; s1[tid >> 5] = a1; }
    __syncthreads();
    if (tid == 0) {
        pred[b * 2 + 0] = s0[0] + s0[1] + s0[2] + s0[3] + outb[0];
        pred[b * 2 + 1] = s1[0] + s1[1] + s1[2] + s1[3] + outb[1];
    }
}

// ---------------- launch ----------------
extern "C" void kernel_launch(void* const* d_in, const int* in_sizes, int n_in,
                              void* d_out, int out_size) {
    const int*   words = (const int*)d_in[0];
    const float* Emb   = (const float*)d_in[1];
    const float* W     = (const float*)d_in[2];
    const float* U     = (const float*)d_in[3];
    const float* bias  = (const float*)d_in[4];
    const float* outW  = (const float*)d_in[5];
    const float* outb  = (const float*)d_in[6];
    float* pred = (float*)d_out;

    cudaFuncSetAttribute(scan_kernel, cudaFuncAttributeMaxDynamicSharedMemorySize, SM_TOTAL);
    cudaFuncSetAttribute(ew_gemm2, cudaFuncAttributeMaxDynamicSharedMemorySize, EW_SMEM);

    reset_kernel<<<256, 256>>>(words);
    ew_gemm2<<<dim3((NDICT + 127) / 128, NGATE / 128), 256, EW_SMEM>>>(Emb, W, bias);
    scan_kernel<<<NBLK, 128, SM_TOTAL>>>(U);
    out_kernel<<<256, 128>>>(outW, outb, pred);
}

// round 14
// speedup vs baseline: 1.6900x; 1.1892x over previous
#include <cuda_runtime.h>
#include <cuda_bf16.h>
#include <cuda_fp16.h>
#include <cstdint>

typedef unsigned long long ull;
typedef unsigned int u32;
typedef unsigned short u16;

// ---------------- constants ----------------
#define NDICT   50000
#define DIN     256
#define DH      256
#define NGATE   1024
#define BB      256
#define SS      512
#define NBLK    128

// ---- scan smem (bytes); pitches conflict-free for ldmatrix
#define AP 264                      // U row pitch in fp16 (33 x 16B)
#define HP 264                      // h row pitch in fp16
#define SM_UH    0
#define SM_HT   (SM_UH + 128 * AP * 2)            // 67584
#define SM_TOTAL (SM_HT + 32 * HP * 2)            // 84480 B

// ---- ew_gemm smem (bytes); fp16 single-dtype, pitch 72 fp16 = 144 B
#define EPH 72
#define EW_A 0
#define EW_B (EW_A + 128 * EPH * 2)               // 18432
#define EW_BIAS (EW_B + 128 * EPH * 2)            // 36864
#define EW_SMEM (EW_BIAS + 128 * 4)               // 37376 B

// ---------------- device scratch ----------------
__device__ float g_EW[(size_t)NDICT * NGATE];  // Emb@W^T + bias, cols permuted j*4+type
__device__ u16   g_hfp16[2 * 2 * BB * DH];     // [buf][dir][b][k] h as fp16
__device__ float g_h[2 * DH * BB];             // final h [dir][j][b] fp32
__device__ int   g_wordsT[SS * BB];
__device__ unsigned g_flags[16 * 64];          // [group(dir,bt)][js*8]

// ---------------- helpers ----------------
__device__ __forceinline__ u32 smem_u32(const void* p) {
    u32 a; asm("{ .reg .u64 t; cvta.to.shared.u64 t, %1; cvt.u32.u64 %0, t; }"
               : "=r"(a) : "l"(p));
    return a;
}
__device__ __forceinline__ float tanha(float x) {
    float r; asm("tanh.approx.f32 %0, %1;" : "=f"(r) : "f"(x)); return r;
}
__device__ __forceinline__ float fsig(float x) {
    return fmaf(tanha(0.5f * x), 0.5f, 0.5f);
}
__device__ __forceinline__ float ftanh(float x) { return tanha(x); }

__device__ __forceinline__ void ldsm4(u32* r, u32 addr) {
    asm volatile("ldmatrix.sync.aligned.m8n8.x4.shared.b16 {%0,%1,%2,%3}, [%4];"
                 : "=r"(r[0]), "=r"(r[1]), "=r"(r[2]), "=r"(r[3]) : "r"(addr));
}
// fp16 x fp16 -> fp32 accumulate
__device__ __forceinline__ void mma16816h(float* c, const u32* a, const u32* b) {
    asm volatile("mma.sync.aligned.m16n8k16.row.col.f32.f16.f16.f32 "
                 "{%0,%1,%2,%3}, {%4,%5,%6,%7}, {%8,%9}, {%0,%1,%2,%3};"
                 : "+f"(c[0]), "+f"(c[1]), "+f"(c[2]), "+f"(c[3])
                 : "r"(a[0]), "r"(a[1]), "r"(a[2]), "r"(a[3]), "r"(b[0]), "r"(b[1]));
}
__device__ __forceinline__ u32 pack2h(float x, float y) {
    __half2 h = __floats2half2_rn(x, y);
    return *(u32*)&h;
}

// ---------------- kernel 0: reset ----------------
__global__ void reset_kernel(const int* __restrict__ words) {
    int idx = blockIdx.x * blockDim.x + threadIdx.x;
    if (idx < 16 * 64) g_flags[idx] = 0u;
    u32* hz = (u32*)g_hfp16;
    for (int i = idx; i < BB * DH; i += gridDim.x * blockDim.x) hz[i] = 0u;
    for (int i = idx; i < SS * BB; i += gridDim.x * blockDim.x) {
        int s = i >> 8, b = i & 255;
        g_wordsT[i] = words[b * SS + s];
    }
}

// ---------------- kernel 1: EW = Emb @ W^T (+bias), fp16 single-pass HMMA ----------------
// grid (391, 8), 256 thr = 8 warps (4m x 2n), CTA tile 128m x 128n, K=256 in 4 chunks
__global__ __launch_bounds__(256) void ew_gemm2(const float* __restrict__ Emb,
                                                const float* __restrict__ W,
                                                const float* __restrict__ bias) {
    extern __shared__ __align__(16) char esm[];
    u32 sb = smem_u32(esm);
    float* biasp = (float*)(esm + EW_BIAS);

    int tid = threadIdx.x;
    int w = tid >> 5, lid = tid & 31;
    int mbase = blockIdx.x * 128;
    int nbase = blockIdx.y * 128;
    int wm = (w & 3) * 32, wn = (w >> 2) * 64;

    if (tid < 128) {
        int colp = nbase + tid;
        biasp[tid] = bias[(colp & 3) * 256 + (colp >> 2)];
    }

    int idx4 = lid >> 3, r8 = lid & 7;
    u32 aoff0 = (u32)(((wm + (idx4 & 1) * 8 + r8) * EPH + (idx4 >> 1) * 8) * 2);
    u32 aoff1 = aoff0 + (u32)(16 * EPH * 2);
    u32 boffB = (u32)(((wn + (idx4 >> 1) * 8 + r8) * EPH + (idx4 & 1) * 8) * 2);

    float acc[2][8][4];
#pragma unroll
    for (int mt = 0; mt < 2; mt++)
#pragma unroll
        for (int n8 = 0; n8 < 8; n8++)
#pragma unroll
            for (int q = 0; q < 4; q++) acc[mt][n8][q] = 0.f;

    for (int kb = 0; kb < 4; kb++) {
        int k0 = kb * 64;
        // stage A (Emb tile) 128 x 64 -> fp16
        for (int i = tid; i < 128 * 16; i += 256) {
            int row = i >> 4, kq = (i & 15) * 4;
            int va = mbase + row;
            float4 v = make_float4(0.f, 0.f, 0.f, 0.f);
            if (va < NDICT) v = *(const float4*)&Emb[(size_t)va * DIN + k0 + kq];
            u32* ap = (u32*)(esm + EW_A + (row * EPH + kq) * 2);
            ap[0] = pack2h(v.x, v.y); ap[1] = pack2h(v.z, v.w);
        }
        // stage B (W tile, permuted rows) 128 x 64 -> fp16
        for (int i = tid; i < 128 * 16; i += 256) {
            int row = i >> 4, kq = (i & 15) * 4;
            int colp = nbase + row;
            int grow = (colp & 3) * 256 + (colp >> 2);
            float4 v = *(const float4*)&W[(size_t)grow * DIN + k0 + kq];
            u32* bp = (u32*)(esm + EW_B + (row * EPH + kq) * 2);
            bp[0] = pack2h(v.x, v.y); bp[1] = pack2h(v.z, v.w);
        }
        __syncthreads();

#pragma unroll
        for (int kt = 0; kt < 4; kt++) {
            u32 koff = (u32)(kt * 32);
            u32 a0[4], a1[4];
            ldsm4(a0, sb + EW_A + aoff0 + koff);
            ldsm4(a1, sb + EW_A + aoff1 + koff);
#pragma unroll
            for (int p = 0; p < 4; p++) {
                u32 po = (u32)(p * 16 * EPH * 2);
                u32 bf[4];
                ldsm4(bf, sb + EW_B + boffB + po + koff);
                mma16816h(acc[0][2 * p + 0], a0, bf + 0);
                mma16816h(acc[0][2 * p + 1], a0, bf + 2);
                mma16816h(acc[1][2 * p + 0], a1, bf + 0);
                mma16816h(acc[1][2 * p + 1], a1, bf + 2);
            }
        }
        __syncthreads();
    }

#pragma unroll
    for (int mt = 0; mt < 2; mt++) {
#pragma unroll
        for (int n8 = 0; n8 < 8; n8++) {
            int nl = wn + n8 * 8 + (lid & 3) * 2;
            int col = nbase + nl;
            float b0 = biasp[nl], b1 = biasp[nl + 1];
            int r0 = mbase + wm + mt * 16 + (lid >> 2);
            if (r0 < NDICT)
                *(float2*)&g_EW[(size_t)r0 * NGATE + col] =
                    make_float2(acc[mt][n8][0] + b0, acc[mt][n8][1] + b1);
            if (r0 + 8 < NDICT)
                *(float2*)&g_EW[(size_t)(r0 + 8) * NGATE + col] =
                    make_float2(acc[mt][n8][2] + b0, acc[mt][n8][3] + b1);
        }
    }
}

// ---------------- kernel 2: persistent scan — fp16 HMMA, pipelined step ----------------
// grid = 128 CTAs: dir(2) x batch-tile(8, 32 rows) x gate-slice(8, 32 j)
// Per step: stage k-half0 | [issue k-half1] MMA half0 | MMA half1 | reg epilogue
__global__ __launch_bounds__(128, 1) void scan_kernel(const float* __restrict__ U) {
    extern __shared__ __align__(16) char smem[];
    u32 sbase = smem_u32(smem);

    int tid = threadIdx.x;
    int w = tid >> 5, lid = tid & 31;
    int bx = blockIdx.x;
    int dir = bx >> 6;
    int bt  = (bx >> 3) & 7;
    int js  = bx & 7;
    int grp = bx >> 3;

    int j = js * 32 + w * 8 + (lid >> 2);   // this thread's hidden unit
    int bcol[8];
#pragma unroll
    for (int r = 0; r < 8; r++) bcol[r] = (r >> 1) * 8 + (lid & 3) * 2 + (r & 1);

    // preload U slice (fp16), rows r = w2*32 + type*8 + jl
    for (int i = tid; i < 128 * 256; i += 128) {
        int r = i >> 8, k = i & 255;
        int w2 = r >> 5, type = (r >> 3) & 3, jl = r & 7;
        float u = U[(size_t)(type * 256 + js * 32 + w2 * 8 + jl) * DH + k];
        *(__half*)(smem + SM_UH + (r * AP + k) * 2) = __float2half_rn(u);
    }

    int idx4 = lid >> 3, r8 = lid & 7;
    u32 aoff0 = (u32)(((w * 32 + (idx4 & 1) * 8 + r8) * AP + (idx4 >> 1) * 8) * 2);
    u32 aoff1 = aoff0 + (u32)(16 * AP * 2);
    u32 boff0 = (u32)((((idx4 >> 1) * 8 + r8) * HP + (idx4 & 1) * 8) * 2);
    u32 boff1 = boff0 + (u32)(16 * HP * 2);

    float c[8];
#pragma unroll
    for (int r = 0; r < 8; r++) c[r] = 0.f;

    // EW prefetch for t=0
    float4 e[8];
    {
        int s0 = dir ? (SS - 1) : 0;
#pragma unroll
        for (int r = 0; r < 8; r++) {
            int wd = g_wordsT[s0 * BB + bt * 32 + bcol[r]];
            e[r] = __ldg((const float4*)&g_EW[(size_t)wd * NGATE + j * 4]);
        }
    }
    __syncthreads();

    for (int t = 0; t < SS; t++) {
        int cur = t & 1, nxt = cur ^ 1;

        const uint4* hb = (const uint4*)(g_hfp16 +
            ((size_t)(cur * 2 + dir) * BB + bt * 32) * DH);

        // ---- stage k-half 0 (k 0..127)
#pragma unroll
        for (int it = 0; it < 4; it++) {
            int i = tid + it * 128;
            int b = i >> 4, c8 = i & 15;
            uint4 v = __ldcg(hb + b * 32 + c8);
            *(uint4*)(smem + SM_HT + (b * HP + c8 * 8) * 2) = v;
        }
        __syncthreads();

        // ---- issue k-half 1 loads+stores (in flight during MMA half 0)
#pragma unroll
        for (int it = 0; it < 4; it++) {
            int i = tid + it * 128;
            int b = i >> 4, c8 = (i & 15) + 16;
            uint4 v = __ldcg(hb + b * 32 + c8);
            *(uint4*)(smem + SM_HT + (b * HP + c8 * 8) * 2) = v;
        }

        float acc[2][4][4];
#pragma unroll
        for (int mt = 0; mt < 2; mt++)
#pragma unroll
            for (int nt = 0; nt < 4; nt++)
#pragma unroll
                for (int q = 0; q < 4; q++) acc[mt][nt][q] = 0.f;

        // ---- MMA k-half 0 (kt 0..7)
#pragma unroll
        for (int kt = 0; kt < 8; kt++) {
            u32 koff = (u32)(kt * 32);
            u32 af0[4], af1[4], bh[8];
            ldsm4(af0, sbase + SM_UH + aoff0 + koff);
            ldsm4(af1, sbase + SM_UH + aoff1 + koff);
            ldsm4(bh,     sbase + SM_HT + boff0 + koff);
            ldsm4(bh + 4, sbase + SM_HT + boff1 + koff);
            mma16816h(acc[0][0], af0, bh + 0);
            mma16816h(acc[0][1], af0, bh + 2);
            mma16816h(acc[0][2], af0, bh + 4);
            mma16816h(acc[0][3], af0, bh + 6);
            mma16816h(acc[1][0], af1, bh + 0);
            mma16816h(acc[1][1], af1, bh + 2);
            mma16816h(acc[1][2], af1, bh + 4);
            mma16816h(acc[1][3], af1, bh + 6);
        }
        __syncthreads();   // half-1 STS drained

        // ---- MMA k-half 1 (kt 8..15)
#pragma unroll
        for (int kt = 8; kt < 16; kt++) {
            u32 koff = (u32)(kt * 32);
            u32 af0[4], af1[4], bh[8];
            ldsm4(af0, sbase + SM_UH + aoff0 + koff);
            ldsm4(af1, sbase + SM_UH + aoff1 + koff);
            ldsm4(bh,     sbase + SM_HT + boff0 + koff);
            ldsm4(bh + 4, sbase + SM_HT + boff1 + koff);
            mma16816h(acc[0][0], af0, bh + 0);
            mma16816h(acc[0][1], af0, bh + 2);
            mma16816h(acc[0][2], af0, bh + 4);
            mma16816h(acc[0][3], af0, bh + 6);
            mma16816h(acc[1][0], af1, bh + 0);
            mma16816h(acc[1][1], af1, bh + 2);
            mma16816h(acc[1][2], af1, bh + 4);
            mma16816h(acc[1][3], af1, bh + 6);
        }

        // ---- register epilogue (MUFU.TANH activations)
        float hout[8];
#pragma unroll
        for (int r = 0; r < 8; r++) {
            int nt = r >> 1, q = r & 1;
            float gi = fsig (acc[0][nt][q]     + e[r].x);
            float gf = fsig (acc[0][nt][2 + q] + e[r].y);
            float go = fsig (acc[1][nt][q]     + e[r].z);
            float gc = ftanh(acc[1][nt][2 + q] + e[r].w);
            c[r] = gf * c[r] + gi * gc;
            hout[r] = go * ftanh(c[r]);
        }

        // store h as fp16 to global [b][k=j]
        u16* hbuf = g_hfp16 + (size_t)(nxt * 2 + dir) * BB * DH + (size_t)bt * 32 * DH + j;
#pragma unroll
        for (int r = 0; r < 8; r++) {
            __half hv = __float2half_rn(hout[r]);
            __stcg((__half*)(hbuf + (size_t)bcol[r] * DH), hv);
        }
        if (t == SS - 1) {
#pragma unroll
            for (int r = 0; r < 8; r++)
                g_h[(size_t)dir * DH * BB + (size_t)j * BB + bt * 32 + bcol[r]] = hout[r];
        }

        __syncthreads();   // all tile reads done, all h stores issued
        if (t < SS - 1) {
            if (tid == 0) {
                asm volatile("st.release.gpu.u32 [%0], %1;"
                             :: "l"(&g_flags[grp * 64 + js * 8]), "r"(t + 1) : "memory");
            }
            // EW prefetch for t+1 — LDGs in flight during the poll
            {
                int sn = dir ? (SS - 2 - t) : (t + 1);
#pragma unroll
                for (int r = 0; r < 8; r++) {
                    int wd = g_wordsT[sn * BB + bt * 32 + bcol[r]];
                    e[r] = __ldg((const float4*)&g_EW[(size_t)wd * NGATE + j * 4]);
                }
            }
            // warp 0 polls the group's 8 flags
            if (tid < 32) {
                unsigned* fp = &g_flags[grp * 64 + (lid & 7) * 8];
                unsigned v;
                do {
                    asm volatile("ld.acquire.gpu.u32 %0, [%1];"
                                 : "=r"(v) : "l"(fp) : "memory");
                } while ((int)v < t + 1);
            }
            __syncthreads();
        }
    }
}

// ---------------- kernel 3: output layer ----------------
__global__ void out_kernel(const float* __restrict__ outW,
                           const float* __restrict__ outb,
                           float* __restrict__ pred) {
    int b = blockIdx.x;
    int tid = threadIdx.x;
    const float* hl = g_h;
    const float* hr = g_h + (size_t)DH * BB;
    float a0 = 0.f, a1 = 0.f;
    for (int idx = tid; idx < 512; idx += 128) {
        float v = (idx < 256) ? hl[idx * BB + b] : hr[(idx - 256) * BB + b];
        a0 += v * outW[idx];
        a1 += v * outW[512 + idx];
    }
#pragma unroll
    for (int o = 16; o > 0; o >>= 1) {
        a0 += __shfl_down_sync(0xFFFFFFFFu, a0, o);
        a1 += __shfl_down_sync(0xFFFFFFFFu, a1, o);
    }
    __shared__ float s0[4], s1[4];
    if ((tid & 31) == 0) { s0[tid >> 5] = a0; s1[tid >> 5] = a1; }
    __syncthreads();
    if (tid == 0) {
        pred[b * 2 + 0] = s0[0] + s0[1] + s0[2] + s0[3] + outb[0];
        pred[b * 2 + 1] = s1[0] + s1[1] + s1[2] + s1[3] + outb[1];
    }
}

// ---------------- launch ----------------
extern "C" void kernel_launch(void* const* d_in, const int* in_sizes, int n_in,
                              void* d_out, int out_size) {
    const int*   words = (const int*)d_in[0];
    const float* Emb   = (const float*)d_in[1];
    const float* W     = (const float*)d_in[2];
    const float* U     = (const float*)d_in[3];
    const float* bias  = (const float*)d_in[4];
    const float* outW  = (const float*)d_in[5];
    const float* outb  = (const float*)d_in[6];
    float* pred = (float*)d_out;

    cudaFuncSetAttribute(scan_kernel, cudaFuncAttributeMaxDynamicSharedMemorySize, SM_TOTAL);
    cudaFuncSetAttribute(ew_gemm2, cudaFuncAttributeMaxDynamicSharedMemorySize, EW_SMEM);

    reset_kernel<<<256, 256>>>(words);
    ew_gemm2<<<dim3((NDICT + 127) / 128, NGATE / 128), 256, EW_SMEM>>>(Emb, W, bias);
    scan_kernel<<<NBLK, 128, SM_TOTAL>>>(U);
    out_kernel<<<256, 128>>>(outW, outb, pred);
}

// round 15
// speedup vs baseline: 1.7838x; 1.0555x over previous
#include <cuda_runtime.h>
#include <cuda_bf16.h>
#include <cuda_fp16.h>
#include <cstdint>

typedef unsigned long long ull;
typedef unsigned int u32;
typedef unsigned short u16;

// ---------------- constants ----------------
#define NDICT   50000
#define DIN     256
#define DH      256
#define NGATE   1024
#define BB      256
#define SS      512
#define NBLK    128
#define BT      16                  // batch rows per CTA
#define JS      64                  // j units per CTA (256 gate rows)

// ---- scan smem (bytes); pitch 264 fp16 = 33 x 16B, conflict-free ldmatrix
#define AP 264
#define SM_UH    0
#define SM_HT   (SM_UH + 256 * AP * 2)            // 135168
#define SM_TOTAL (SM_HT + BT * AP * 2)            // 143616 B

// ---- ew_gemm smem (bytes); fp16 single-dtype, pitch 72 fp16 = 144 B
#define EPH 72
#define EW_A 0
#define EW_B (EW_A + 128 * EPH * 2)               // 18432
#define EW_BIAS (EW_B + 128 * EPH * 2)            // 36864
#define EW_SMEM (EW_BIAS + 128 * 4)               // 37376 B

// ---------------- device scratch ----------------
__device__ float g_EW[(size_t)NDICT * NGATE];  // Emb@W^T + bias, cols permuted j*4+type
__device__ u16   g_hfp16[2 * 2 * BB * DH];     // [buf][dir][b][k] h as fp16
__device__ float g_h[2 * DH * BB];             // final h [dir][j][b] fp32
__device__ int   g_wordsT[SS * BB];
__device__ unsigned g_flags[32 * 32];          // [group(dir,bt)][js*8]

// ---------------- helpers ----------------
__device__ __forceinline__ u32 smem_u32(const void* p) {
    u32 a; asm("{ .reg .u64 t; cvta.to.shared.u64 t, %1; cvt.u32.u64 %0, t; }"
               : "=r"(a) : "l"(p));
    return a;
}
__device__ __forceinline__ float tanha(float x) {
    float r; asm("tanh.approx.f32 %0, %1;" : "=f"(r) : "f"(x)); return r;
}
__device__ __forceinline__ float fsig(float x) {
    return fmaf(tanha(0.5f * x), 0.5f, 0.5f);
}
__device__ __forceinline__ float ftanh(float x) { return tanha(x); }

__device__ __forceinline__ void ldsm4(u32* r, u32 addr) {
    asm volatile("ldmatrix.sync.aligned.m8n8.x4.shared.b16 {%0,%1,%2,%3}, [%4];"
                 : "=r"(r[0]), "=r"(r[1]), "=r"(r[2]), "=r"(r[3]) : "r"(addr));
}
// fp16 x fp16 -> fp32 accumulate
__device__ __forceinline__ void mma16816h(float* c, const u32* a, const u32* b) {
    asm volatile("mma.sync.aligned.m16n8k16.row.col.f32.f16.f16.f32 "
                 "{%0,%1,%2,%3}, {%4,%5,%6,%7}, {%8,%9}, {%0,%1,%2,%3};"
                 : "+f"(c[0]), "+f"(c[1]), "+f"(c[2]), "+f"(c[3])
                 : "r"(a[0]), "r"(a[1]), "r"(a[2]), "r"(a[3]), "r"(b[0]), "r"(b[1]));
}
__device__ __forceinline__ u32 pack2h(float x, float y) {
    __half2 h = __floats2half2_rn(x, y);
    return *(u32*)&h;
}

// ---------------- kernel 0: reset ----------------
__global__ void reset_kernel(const int* __restrict__ words) {
    int idx = blockIdx.x * blockDim.x + threadIdx.x;
    if (idx < 32 * 32) g_flags[idx] = 0u;
    u32* hz = (u32*)g_hfp16;
    for (int i = idx; i < BB * DH; i += gridDim.x * blockDim.x) hz[i] = 0u;
    for (int i = idx; i < SS * BB; i += gridDim.x * blockDim.x) {
        int s = i >> 8, b = i & 255;
        g_wordsT[i] = words[b * SS + s];
    }
}

// ---------------- kernel 1: EW = Emb @ W^T (+bias), fp16 single-pass HMMA ----------------
__global__ __launch_bounds__(256) void ew_gemm2(const float* __restrict__ Emb,
                                                const float* __restrict__ W,
                                                const float* __restrict__ bias) {
    extern __shared__ __align__(16) char esm[];
    u32 sb = smem_u32(esm);
    float* biasp = (float*)(esm + EW_BIAS);

    int tid = threadIdx.x;
    int w = tid >> 5, lid = tid & 31;
    int mbase = blockIdx.x * 128;
    int nbase = blockIdx.y * 128;
    int wm = (w & 3) * 32, wn = (w >> 2) * 64;

    if (tid < 128) {
        int colp = nbase + tid;
        biasp[tid] = bias[(colp & 3) * 256 + (colp >> 2)];
    }

    int idx4 = lid >> 3, r8 = lid & 7;
    u32 aoff0 = (u32)(((wm + (idx4 & 1) * 8 + r8) * EPH + (idx4 >> 1) * 8) * 2);
    u32 aoff1 = aoff0 + (u32)(16 * EPH * 2);
    u32 boffB = (u32)(((wn + (idx4 >> 1) * 8 + r8) * EPH + (idx4 & 1) * 8) * 2);

    float acc[2][8][4];
#pragma unroll
    for (int mt = 0; mt < 2; mt++)
#pragma unroll
        for (int n8 = 0; n8 < 8; n8++)
#pragma unroll
            for (int q = 0; q < 4; q++) acc[mt][n8][q] = 0.f;

    for (int kb = 0; kb < 4; kb++) {
        int k0 = kb * 64;
        for (int i = tid; i < 128 * 16; i += 256) {
            int row = i >> 4, kq = (i & 15) * 4;
            int va = mbase + row;
            float4 v = make_float4(0.f, 0.f, 0.f, 0.f);
            if (va < NDICT) v = *(const float4*)&Emb[(size_t)va * DIN + k0 + kq];
            u32* ap = (u32*)(esm + EW_A + (row * EPH + kq) * 2);
            ap[0] = pack2h(v.x, v.y); ap[1] = pack2h(v.z, v.w);
        }
        for (int i = tid; i < 128 * 16; i += 256) {
            int row = i >> 4, kq = (i & 15) * 4;
            int colp = nbase + row;
            int grow = (colp & 3) * 256 + (colp >> 2);
            float4 v = *(const float4*)&W[(size_t)grow * DIN + k0 + kq];
            u32* bp = (u32*)(esm + EW_B + (row * EPH + kq) * 2);
            bp[0] = pack2h(v.x, v.y); bp[1] = pack2h(v.z, v.w);
        }
        __syncthreads();

#pragma unroll
        for (int kt = 0; kt < 4; kt++) {
            u32 koff = (u32)(kt * 32);
            u32 a0[4], a1[4];
            ldsm4(a0, sb + EW_A + aoff0 + koff);
            ldsm4(a1, sb + EW_A + aoff1 + koff);
#pragma unroll
            for (int p = 0; p < 4; p++) {
                u32 po = (u32)(p * 16 * EPH * 2);
                u32 bf[4];
                ldsm4(bf, sb + EW_B + boffB + po + koff);
                mma16816h(acc[0][2 * p + 0], a0, bf + 0);
                mma16816h(acc[0][2 * p + 1], a0, bf + 2);
                mma16816h(acc[1][2 * p + 0], a1, bf + 0);
                mma16816h(acc[1][2 * p + 1], a1, bf + 2);
            }
        }
        __syncthreads();
    }

#pragma unroll
    for (int mt = 0; mt < 2; mt++) {
#pragma unroll
        for (int n8 = 0; n8 < 8; n8++) {
            int nl = wn + n8 * 8 + (lid & 3) * 2;
            int col = nbase + nl;
            float b0 = biasp[nl], b1 = biasp[nl + 1];
            int r0 = mbase + wm + mt * 16 + (lid >> 2);
            if (r0 < NDICT)
                *(float2*)&g_EW[(size_t)r0 * NGATE + col] =
                    make_float2(acc[mt][n8][0] + b0, acc[mt][n8][1] + b1);
            if (r0 + 8 < NDICT)
                *(float2*)&g_EW[(size_t)(r0 + 8) * NGATE + col] =
                    make_float2(acc[mt][n8][2] + b0, acc[mt][n8][3] + b1);
        }
    }
}

// ---------------- kernel 2: persistent scan — fp16 HMMA, js=4 partition ----------------
// grid = 128 CTAs: dir(2) x batch-tile(16, 16 rows) x gate-slice(4, 64 j / 256 rows)
// Warp w owns rows w*64 + type*16 + jl (4 types x 16 jl); N=16 batch.
__global__ __launch_bounds__(128, 1) void scan_kernel(const float* __restrict__ U) {
    extern __shared__ __align__(16) char smem[];
    u32 sbase = smem_u32(smem);

    int tid = threadIdx.x;
    int w = tid >> 5, lid = tid & 31;
    int bx = blockIdx.x;
    int dir = bx >> 6;
    int bt  = (bx >> 2) & 15;
    int js  = bx & 3;
    int grp = bx >> 2;                      // (dir,bt): 32 groups of 4 CTAs

    // thread cell ownership: j = js*64 + w*16 + (lid>>2) + 8q, b = nt*8 + (lid&3)*2 + p
    int jbase = js * 64 + w * 16 + (lid >> 2);
    int bcol[4];                             // cellb = nt*2+p -> local batch col
#pragma unroll
    for (int cb = 0; cb < 4; cb++) bcol[cb] = (cb >> 1) * 8 + (lid & 3) * 2 + (cb & 1);

    // preload U slice (fp16): rows r = w2*64 + type*16 + jl  (256 rows x 256 k)
    for (int i = tid; i < 256 * 256; i += 128) {
        int r = i >> 8, k = i & 255;
        int w2 = r >> 6, type = (r >> 4) & 3, jl = r & 15;
        float u = U[(size_t)(type * 256 + js * 64 + w2 * 16 + jl) * DH + k];
        *(__half*)(smem + SM_UH + (r * AP + k) * 2) = __float2half_rn(u);
    }

    int idx4 = lid >> 3, r8 = lid & 7;
    u32 aoff[4];
#pragma unroll
    for (int mt = 0; mt < 4; mt++)
        aoff[mt] = (u32)(((w * 64 + mt * 16 + (idx4 & 1) * 8 + r8) * AP + (idx4 >> 1) * 8) * 2);
    u32 boff = (u32)((((idx4 >> 1) * 8 + r8) * AP + (idx4 & 1) * 8) * 2);

    float c[8];
#pragma unroll
    for (int r = 0; r < 8; r++) c[r] = 0.f;

    // EW prefetch for t=0: e[r], r = q*4 + cb  (j = jbase+8q, b = bcol[cb])
    float4 e[8];
    {
        int s0 = dir ? (SS - 1) : 0;
#pragma unroll
        for (int r = 0; r < 8; r++) {
            int q = r >> 2, cb = r & 3;
            int wd = g_wordsT[s0 * BB + bt * BT + bcol[cb]];
            e[r] = __ldg((const float4*)&g_EW[(size_t)wd * NGATE + (jbase + 8 * q) * 4]);
        }
    }
    __syncthreads();

    for (int t = 0; t < SS; t++) {
        int cur = t & 1, nxt = cur ^ 1;

        const uint4* hb = (const uint4*)(g_hfp16 +
            ((size_t)(cur * 2 + dir) * BB + bt * BT) * DH);

        // ---- stage k-half 0 (k 0..127): 16 b x 16 uint4
#pragma unroll
        for (int it = 0; it < 2; it++) {
            int i = tid + it * 128;
            int b = i >> 4, c8 = i & 15;
            uint4 v = __ldcg(hb + b * 32 + c8);
            *(uint4*)(smem + SM_HT + (b * AP + c8 * 8) * 2) = v;
        }
        __syncthreads();

        // ---- issue k-half 1 loads+stores (in flight during MMA half 0)
#pragma unroll
        for (int it = 0; it < 2; it++) {
            int i = tid + it * 128;
            int b = i >> 4, c8 = (i & 15) + 16;
            uint4 v = __ldcg(hb + b * 32 + c8);
            *(uint4*)(smem + SM_HT + (b * AP + c8 * 8) * 2) = v;
        }

        float acc[4][2][4];                  // [type(mt)][nt][elem]
#pragma unroll
        for (int mt = 0; mt < 4; mt++)
#pragma unroll
            for (int nt = 0; nt < 2; nt++)
#pragma unroll
                for (int q = 0; q < 4; q++) acc[mt][nt][q] = 0.f;

        // ---- MMA k-half 0 (kt 0..7)
#pragma unroll
        for (int kt = 0; kt < 8; kt++) {
            u32 koff = (u32)(kt * 32);
            u32 bf[4];
            ldsm4(bf, sbase + SM_HT + boff + koff);
#pragma unroll
            for (int mt = 0; mt < 4; mt++) {
                u32 af[4];
                ldsm4(af, sbase + SM_UH + aoff[mt] + koff);
                mma16816h(acc[mt][0], af, bf + 0);
                mma16816h(acc[mt][1], af, bf + 2);
            }
        }
        __syncthreads();   // half-1 STS drained

        // ---- MMA k-half 1 (kt 8..15)
#pragma unroll
        for (int kt = 8; kt < 16; kt++) {
            u32 koff = (u32)(kt * 32);
            u32 bf[4];
            ldsm4(bf, sbase + SM_HT + boff + koff);
#pragma unroll
            for (int mt = 0; mt < 4; mt++) {
                u32 af[4];
                ldsm4(af, sbase + SM_UH + aoff[mt] + koff);
                mma16816h(acc[mt][0], af, bf + 0);
                mma16816h(acc[mt][1], af, bf + 2);
            }
        }

        // ---- register epilogue: cell r = q*4 + cb, gate type mt value = acc[mt][nt][2q+p]
        float hout[8];
#pragma unroll
        for (int r = 0; r < 8; r++) {
            int q = r >> 2, cb = r & 3;
            int nt = cb >> 1, p = cb & 1;
            int el = 2 * q + p;
            float gi = fsig (acc[0][nt][el] + e[r].x);
            float gf = fsig (acc[1][nt][el] + e[r].y);
            float go = fsig (acc[2][nt][el] + e[r].z);
            float gc = ftanh(acc[3][nt][el] + e[r].w);
            c[r] = gf * c[r] + gi * gc;
            hout[r] = go * ftanh(c[r]);
        }

        // store h as fp16 to global [b][k=j]
        u16* hbuf = g_hfp16 + (size_t)(nxt * 2 + dir) * BB * DH + (size_t)bt * BT * DH;
#pragma unroll
        for (int r = 0; r < 8; r++) {
            int q = r >> 2, cb = r & 3;
            __half hv = __float2half_rn(hout[r]);
            __stcg((__half*)(hbuf + (size_t)bcol[cb] * DH + jbase + 8 * q), hv);
        }
        if (t == SS - 1) {
#pragma unroll
            for (int r = 0; r < 8; r++) {
                int q = r >> 2, cb = r & 3;
                g_h[(size_t)dir * DH * BB + (size_t)(jbase + 8 * q) * BB + bt * BT + bcol[cb]] = hout[r];
            }
        }

        __syncthreads();   // all tile reads done, all h stores issued
        if (t < SS - 1) {
            if (tid == 0) {
                asm volatile("st.release.gpu.u32 [%0], %1;"
                             :: "l"(&g_flags[grp * 32 + js * 8]), "r"(t + 1) : "memory");
            }
            // EW prefetch for t+1 — LDGs in flight during the poll
            {
                int sn = dir ? (SS - 2 - t) : (t + 1);
#pragma unroll
                for (int r = 0; r < 8; r++) {
                    int q = r >> 2, cb = r & 3;
                    int wd = g_wordsT[sn * BB + bt * BT + bcol[cb]];
                    e[r] = __ldg((const float4*)&g_EW[(size_t)wd * NGATE + (jbase + 8 * q) * 4]);
                }
            }
            // warp 0 polls the group's 4 flags
            if (tid < 32) {
                unsigned* fp = &g_flags[grp * 32 + (lid & 3) * 8];
                unsigned v;
                do {
                    asm volatile("ld.acquire.gpu.u32 %0, [%1];"
                                 : "=r"(v) : "l"(fp) : "memory");
                } while ((int)v < t + 1);
            }
            __syncthreads();
        }
    }
}

// ---------------- kernel 3: output layer ----------------
__global__ void out_kernel(const float* __restrict__ outW,
                           const float* __restrict__ outb,
                           float* __restrict__ pred) {
    int b = blockIdx.x;
    int tid = threadIdx.x;
    const float* hl = g_h;
    const float* hr = g_h + (size_t)DH * BB;
    float a0 = 0.f, a1 = 0.f;
    for (int idx = tid; idx < 512; idx += 128) {
        float v = (idx < 256) ? hl[idx * BB + b] : hr[(idx - 256) * BB + b];
        a0 += v * outW[idx];
        a1 += v * outW[512 + idx];
    }
#pragma unroll
    for (int o = 16; o > 0; o >>= 1) {
        a0 += __shfl_down_sync(0xFFFFFFFFu, a0, o);
        a1 += __shfl_down_sync(0xFFFFFFFFu, a1, o);
    }
    __shared__ float s0[4], s1[4];
    if ((tid & 31) == 0) { s0[tid >> 5] = a0; s1[tid >> 5] = a1; }
    __syncthreads();
    if (tid == 0) {
        pred[b * 2 + 0] = s0[0] + s0[1] + s0[2] + s0[3] + outb[0];
        pred[b * 2 + 1] = s1[0] + s1[1] + s1[2] + s1[3] + outb[1];
    }
}

// ---------------- launch ----------------
extern "C" void kernel_launch(void* const* d_in, const int* in_sizes, int n_in,
                              void* d_out, int out_size) {
    const int*   words = (const int*)d_in[0];
    const float* Emb   = (const float*)d_in[1];
    const float* W     = (const float*)d_in[2];
    const float* U     = (const float*)d_in[3];
    const float* bias  = (const float*)d_in[4];
    const float* outW  = (const float*)d_in[5];
    const float* outb  = (const float*)d_in[6];
    float* pred = (float*)d_out;

    cudaFuncSetAttribute(scan_kernel, cudaFuncAttributeMaxDynamicSharedMemorySize, SM_TOTAL);
    cudaFuncSetAttribute(ew_gemm2, cudaFuncAttributeMaxDynamicSharedMemorySize, EW_SMEM);

    reset_kernel<<<256, 256>>>(words);
    ew_gemm2<<<dim3((NDICT + 127) / 128, NGATE / 128), 256, EW_SMEM>>>(Emb, W, bias);
    scan_kernel<<<NBLK, 128, SM_TOTAL>>>(U);
    out_kernel<<<256, 128>>>(outW, outb, pred);
}

// round 16
// speedup vs baseline: 2.6095x; 1.4629x over previous
#include <cuda_runtime.h>
#include <cuda_bf16.h>
#include <cuda_fp16.h>
#include <cstdint>

typedef unsigned long long ull;
typedef unsigned int u32;
typedef unsigned short u16;

// ---------------- constants ----------------
#define NDICT   50000
#define DIN     256
#define DH      256
#define NGATE   1024
#define BB      256
#define SS      512
#define NBLK    128
#define BT      16                  // batch rows per CTA
#define CLS     4                   // cluster size = CTAs per (dir,bt) group

// ---- scan smem (bytes); pitch 264 fp16 = 33 x 16B, conflict-free ldmatrix
#define AP 264
#define SM_UH    0
#define SM_HT0  (SM_UH + 256 * AP * 2)            // 135168
#define SM_HT1  (SM_HT0 + BT * AP * 2)            // 143616
#define SM_MBAR (SM_HT1 + BT * AP * 2)            // 152064
#define SM_TOTAL (SM_MBAR + 64)                   // 152128 B

// ---- ew_gemm smem (bytes); fp16 single-dtype, pitch 72 fp16 = 144 B
#define EPH 72
#define EW_A 0
#define EW_B (EW_A + 128 * EPH * 2)
#define EW_BIAS (EW_B + 128 * EPH * 2)
#define EW_SMEM (EW_BIAS + 128 * 4)

// ---------------- device scratch ----------------
__device__ float g_EW[(size_t)NDICT * NGATE];  // Emb@W^T + bias, cols permuted j*4+type
__device__ float g_h[2 * DH * BB];             // final h [dir][j][b] fp32
__device__ int   g_wordsT[SS * BB];

// ---------------- helpers ----------------
__device__ __forceinline__ u32 smem_u32(const void* p) {
    u32 a; asm("{ .reg .u64 t; cvta.to.shared.u64 t, %1; cvt.u32.u64 %0, t; }"
               : "=r"(a) : "l"(p));
    return a;
}
__device__ __forceinline__ float tanha(float x) {
    float r; asm("tanh.approx.f32 %0, %1;" : "=f"(r) : "f"(x)); return r;
}
__device__ __forceinline__ float fsig(float x) {
    return fmaf(tanha(0.5f * x), 0.5f, 0.5f);
}
__device__ __forceinline__ float ftanh(float x) { return tanha(x); }

__device__ __forceinline__ void ldsm4(u32* r, u32 addr) {
    asm volatile("ldmatrix.sync.aligned.m8n8.x4.shared.b16 {%0,%1,%2,%3}, [%4];"
                 : "=r"(r[0]), "=r"(r[1]), "=r"(r[2]), "=r"(r[3]) : "r"(addr));
}
__device__ __forceinline__ void mma16816h(float* c, const u32* a, const u32* b) {
    asm volatile("mma.sync.aligned.m16n8k16.row.col.f32.f16.f16.f32 "
                 "{%0,%1,%2,%3}, {%4,%5,%6,%7}, {%8,%9}, {%0,%1,%2,%3};"
                 : "+f"(c[0]), "+f"(c[1]), "+f"(c[2]), "+f"(c[3])
                 : "r"(a[0]), "r"(a[1]), "r"(a[2]), "r"(a[3]), "r"(b[0]), "r"(b[1]));
}
__device__ __forceinline__ u32 pack2h(float x, float y) {
    __half2 h = __floats2half2_rn(x, y);
    return *(u32*)&h;
}
__device__ __forceinline__ u32 mapa_peer(u32 local_addr, u32 rank) {
    u32 r;
    asm("mapa.shared::cluster.u32 %0, %1, %2;" : "=r"(r) : "r"(local_addr), "r"(rank));
    return r;
}
__device__ __forceinline__ void st_cluster_u16(u32 addr, u16 v) {
    asm volatile("st.shared::cluster.u16 [%0], %1;" :: "r"(addr), "h"(v) : "memory");
}
__device__ __forceinline__ void mbar_arrive_cluster(u32 addr) {
    asm volatile("mbarrier.arrive.shared::cluster.b64 _, [%0];" :: "r"(addr) : "memory");
}
__device__ __forceinline__ void mbar_wait_cluster(u32 mb, u32 parity) {
    asm volatile(
        "{\n\t.reg .pred P1;\n\t"
        "WAIT_LOOP_%=:\n\t"
        "mbarrier.try_wait.parity.acquire.cluster.shared::cta.b64 P1, [%0], %1, 0x989680;\n\t"
        "@P1 bra.uni WAIT_DONE_%=;\n\t"
        "bra.uni WAIT_LOOP_%=;\n\t"
        "WAIT_DONE_%=:\n\t}"
        :: "r"(mb), "r"(parity) : "memory");
}
#define MBAR_INIT(mb, n)  asm volatile("mbarrier.init.shared.b64 [%0], %1;" :: "r"(mb), "r"(n) : "memory")
#define CLUSTER_SYNC() do { \
    asm volatile("barrier.cluster.arrive.aligned;" ::: "memory"); \
    asm volatile("barrier.cluster.wait.aligned;" ::: "memory"); \
} while (0)

// ---------------- kernel 0: reset ----------------
__global__ void reset_kernel(const int* __restrict__ words) {
    int idx = blockIdx.x * blockDim.x + threadIdx.x;
    for (int i = idx; i < SS * BB; i += gridDim.x * blockDim.x) {
        int s = i >> 8, b = i & 255;
        g_wordsT[i] = words[b * SS + s];
    }
}

// ---------------- kernel 1: EW = Emb @ W^T (+bias), fp16 single-pass HMMA ----------------
__global__ __launch_bounds__(256) void ew_gemm2(const float* __restrict__ Emb,
                                                const float* __restrict__ W,
                                                const float* __restrict__ bias) {
    extern __shared__ __align__(16) char esm[];
    u32 sb = smem_u32(esm);
    float* biasp = (float*)(esm + EW_BIAS);

    int tid = threadIdx.x;
    int w = tid >> 5, lid = tid & 31;
    int mbase = blockIdx.x * 128;
    int nbase = blockIdx.y * 128;
    int wm = (w & 3) * 32, wn = (w >> 2) * 64;

    if (tid < 128) {
        int colp = nbase + tid;
        biasp[tid] = bias[(colp & 3) * 256 + (colp >> 2)];
    }

    int idx4 = lid >> 3, r8 = lid & 7;
    u32 aoff0 = (u32)(((wm + (idx4 & 1) * 8 + r8) * EPH + (idx4 >> 1) * 8) * 2);
    u32 aoff1 = aoff0 + (u32)(16 * EPH * 2);
    u32 boffB = (u32)(((wn + (idx4 >> 1) * 8 + r8) * EPH + (idx4 & 1) * 8) * 2);

    float acc[2][8][4];
#pragma unroll
    for (int mt = 0; mt < 2; mt++)
#pragma unroll
        for (int n8 = 0; n8 < 8; n8++)
#pragma unroll
            for (int q = 0; q < 4; q++) acc[mt][n8][q] = 0.f;

    for (int kb = 0; kb < 4; kb++) {
        int k0 = kb * 64;
        for (int i = tid; i < 128 * 16; i += 256) {
            int row = i >> 4, kq = (i & 15) * 4;
            int va = mbase + row;
            float4 v = make_float4(0.f, 0.f, 0.f, 0.f);
            if (va < NDICT) v = *(const float4*)&Emb[(size_t)va * DIN + k0 + kq];
            u32* ap = (u32*)(esm + EW_A + (row * EPH + kq) * 2);
            ap[0] = pack2h(v.x, v.y); ap[1] = pack2h(v.z, v.w);
        }
        for (int i = tid; i < 128 * 16; i += 256) {
            int row = i >> 4, kq = (i & 15) * 4;
            int colp = nbase + row;
            int grow = (colp & 3) * 256 + (colp >> 2);
            float4 v = *(const float4*)&W[(size_t)grow * DIN + k0 + kq];
            u32* bp = (u32*)(esm + EW_B + (row * EPH + kq) * 2);
            bp[0] = pack2h(v.x, v.y); bp[1] = pack2h(v.z, v.w);
        }
        __syncthreads();

#pragma unroll
        for (int kt = 0; kt < 4; kt++) {
            u32 koff = (u32)(kt * 32);
            u32 a0[4], a1[4];
            ldsm4(a0, sb + EW_A + aoff0 + koff);
            ldsm4(a1, sb + EW_A + aoff1 + koff);
#pragma unroll
            for (int p = 0; p < 4; p++) {
                u32 po = (u32)(p * 16 * EPH * 2);
                u32 bf[4];
                ldsm4(bf, sb + EW_B + boffB + po + koff);
                mma16816h(acc[0][2 * p + 0], a0, bf + 0);
                mma16816h(acc[0][2 * p + 1], a0, bf + 2);
                mma16816h(acc[1][2 * p + 0], a1, bf + 0);
                mma16816h(acc[1][2 * p + 1], a1, bf + 2);
            }
        }
        __syncthreads();
    }

#pragma unroll
    for (int mt = 0; mt < 2; mt++) {
#pragma unroll
        for (int n8 = 0; n8 < 8; n8++) {
            int nl = wn + n8 * 8 + (lid & 3) * 2;
            int col = nbase + nl;
            float b0 = biasp[nl], b1 = biasp[nl + 1];
            int r0 = mbase + wm + mt * 16 + (lid >> 2);
            if (r0 < NDICT)
                *(float2*)&g_EW[(size_t)r0 * NGATE + col] =
                    make_float2(acc[mt][n8][0] + b0, acc[mt][n8][1] + b1);
            if (r0 + 8 < NDICT)
                *(float2*)&g_EW[(size_t)(r0 + 8) * NGATE + col] =
                    make_float2(acc[mt][n8][2] + b0, acc[mt][n8][3] + b1);
        }
    }
}

// ---------------- kernel 2: persistent scan — cluster DSMEM h exchange ----------------
// grid = 128 CTAs, cluster(4): dir(2) x batch-tile(16, 16 rows) x gate-slice(4, 64 j)
// h is exchanged via st.shared::cluster into double-buffered peer staging tiles.
__global__ __launch_bounds__(128, 1) __cluster_dims__(CLS, 1, 1)
void scan_kernel(const float* __restrict__ U) {
    extern __shared__ __align__(16) char smem[];
    u32 sbase = smem_u32(smem);

    int tid = threadIdx.x;
    int w = tid >> 5, lid = tid & 31;
    int bx = blockIdx.x;
    int dir = bx >> 6;
    int bt  = (bx >> 2) & 15;
    int js  = bx & 3;                        // == cluster rank

    int jbase = js * 64 + w * 16 + (lid >> 2);
    int bcol[4];
#pragma unroll
    for (int cb = 0; cb < 4; cb++) bcol[cb] = (cb >> 1) * 8 + (lid & 3) * 2 + (cb & 1);

    // mbarrier: 512 arrivals per step (128 threads x 4 cluster CTAs)
    if (tid == 0) { MBAR_INIT(sbase + SM_MBAR, 512u); }

    // zero both h staging buffers (t=0 reads zeros; h0 = 0)
    for (int i = tid; i < (2 * BT * AP * 2) / 4; i += 128)
        ((u32*)(smem + SM_HT0))[i] = 0u;

    // preload U slice (fp16): rows r = w2*64 + type*16 + jl  (256 rows x 256 k)
    for (int i = tid; i < 256 * 256; i += 128) {
        int r = i >> 8, k = i & 255;
        int w2 = r >> 6, type = (r >> 4) & 3, jl = r & 15;
        float u = U[(size_t)(type * 256 + js * 64 + w2 * 16 + jl) * DH + k];
        *(__half*)(smem + SM_UH + (r * AP + k) * 2) = __float2half_rn(u);
    }

    int idx4 = lid >> 3, r8 = lid & 7;
    u32 aoff[4];
#pragma unroll
    for (int mt = 0; mt < 4; mt++)
        aoff[mt] = (u32)(((w * 64 + mt * 16 + (idx4 & 1) * 8 + r8) * AP + (idx4 >> 1) * 8) * 2);
    u32 boff = (u32)((((idx4 >> 1) * 8 + r8) * AP + (idx4 & 1) * 8) * 2);

    // peer SMEM base addresses (same offsets valid in every cluster CTA)
    u32 peerbase[CLS];
#pragma unroll
    for (int p = 0; p < CLS; p++) peerbase[p] = mapa_peer(sbase, (u32)p);

    // per-cell staging offsets (within a buffer)
    u32 celloff[8];
#pragma unroll
    for (int r = 0; r < 8; r++) {
        int q = r >> 2, cb = r & 3;
        celloff[r] = (u32)((bcol[cb] * AP + jbase + 8 * q) * 2);
    }

    float c[8];
#pragma unroll
    for (int r = 0; r < 8; r++) c[r] = 0.f;

    // EW prefetch for t=0
    float4 e[8];
    {
        int s0 = dir ? (SS - 1) : 0;
#pragma unroll
        for (int r = 0; r < 8; r++) {
            int q = r >> 2, cb = r & 3;
            int wd = g_wordsT[s0 * BB + bt * BT + bcol[cb]];
            e[r] = __ldg((const float4*)&g_EW[(size_t)wd * NGATE + (jbase + 8 * q) * 4]);
        }
    }
    __syncthreads();      // smem init + U preload complete (CTA-local)
    CLUSTER_SYNC();       // mbarriers + buffers visible cluster-wide

    for (int t = 0; t < SS; t++) {
        u32 bufr = sbase + ((t & 1) ? SM_HT1 : SM_HT0);

        // wait for all 4 CTAs' h(t) deposits (completion #t, parity (t-1)&1)
        if (t > 0) mbar_wait_cluster(sbase + SM_MBAR, (u32)((t - 1) & 1));

        // ---- MMA: 256 gate rows x 16 batch, K=256 (data already resident)
        float acc[4][2][4];
#pragma unroll
        for (int mt = 0; mt < 4; mt++)
#pragma unroll
            for (int nt = 0; nt < 2; nt++)
#pragma unroll
                for (int q = 0; q < 4; q++) acc[mt][nt][q] = 0.f;

#pragma unroll
        for (int kt = 0; kt < 16; kt++) {
            u32 koff = (u32)(kt * 32);
            u32 bf[4];
            ldsm4(bf, bufr + boff + koff);
#pragma unroll
            for (int mt = 0; mt < 4; mt++) {
                u32 af[4];
                ldsm4(af, sbase + SM_UH + aoff[mt] + koff);
                mma16816h(acc[mt][0], af, bf + 0);
                mma16816h(acc[mt][1], af, bf + 2);
            }
        }

        // ---- register epilogue
        float hout[8];
#pragma unroll
        for (int r = 0; r < 8; r++) {
            int q = r >> 2, cb = r & 3;
            int nt = cb >> 1, p = cb & 1;
            int el = 2 * q + p;
            float gi = fsig (acc[0][nt][el] + e[r].x);
            float gf = fsig (acc[1][nt][el] + e[r].y);
            float go = fsig (acc[2][nt][el] + e[r].z);
            float gc = ftanh(acc[3][nt][el] + e[r].w);
            c[r] = gf * c[r] + gi * gc;
            hout[r] = go * ftanh(c[r]);
        }

        if (t < SS - 1) {
            u32 bufw_off = (u32)(((t & 1) ^ 1) ? SM_HT1 : SM_HT0);
            u16 hv[8];
#pragma unroll
            for (int r = 0; r < 8; r++) {
                __half h = __float2half_rn(hout[r]);
                hv[r] = *(u16*)&h;
            }
            // deposit h(t+1) into all 4 peers' write buffer, then arrive
#pragma unroll
            for (int p = 0; p < CLS; p++) {
                u32 pb = peerbase[p] + bufw_off;
#pragma unroll
                for (int r = 0; r < 8; r++) st_cluster_u16(pb + celloff[r], hv[r]);
                mbar_arrive_cluster(peerbase[p] + SM_MBAR);
            }
            // EW prefetch for t+1 (in flight under next wait)
            {
                int sn = dir ? (SS - 2 - t) : (t + 1);
#pragma unroll
                for (int r = 0; r < 8; r++) {
                    int q = r >> 2, cb = r & 3;
                    int wd = g_wordsT[sn * BB + bt * BT + bcol[cb]];
                    e[r] = __ldg((const float4*)&g_EW[(size_t)wd * NGATE + (jbase + 8 * q) * 4]);
                }
            }
        } else {
#pragma unroll
            for (int r = 0; r < 8; r++) {
                int q = r >> 2, cb = r & 3;
                g_h[(size_t)dir * DH * BB + (size_t)(jbase + 8 * q) * BB + bt * BT + bcol[cb]] = hout[r];
            }
        }
    }

    CLUSTER_SYNC();   // no CTA exits while peers may still reference its SMEM
}

// ---------------- kernel 3: output layer ----------------
__global__ void out_kernel(const float* __restrict__ outW,
                           const float* __restrict__ outb,
                           float* __restrict__ pred) {
    int b = blockIdx.x;
    int tid = threadIdx.x;
    const float* hl = g_h;
    const float* hr = g_h + (size_t)DH * BB;
    float a0 = 0.f, a1 = 0.f;
    for (int idx = tid; idx < 512; idx += 128) {
        float v = (idx < 256) ? hl[idx * BB + b] : hr[(idx - 256) * BB + b];
        a0 += v * outW[idx];
        a1 += v * outW[512 + idx];
    }
#pragma unroll
    for (int o = 16; o > 0; o >>= 1) {
        a0 += __shfl_down_sync(0xFFFFFFFFu, a0, o);
        a1 += __shfl_down_sync(0xFFFFFFFFu, a1, o);
    }
    __shared__ float s0[4], s1[4];
    if ((tid & 31) == 0) { s0[tid >> 5] = a0; s1[tid >> 5] = a1; }
    __syncthreads();
    if (tid == 0) {
        pred[b * 2 + 0] = s0[0] + s0[1] + s0[2] + s0[3] + outb[0];
        pred[b * 2 + 1] = s1[0] + s1[1] + s1[2] + s1[3] + outb[1];
    }
}

// ---------------- launch ----------------
extern "C" void kernel_launch(void* const* d_in, const int* in_sizes, int n_in,
                              void* d_out, int out_size) {
    const int*   words = (const int*)d_in[0];
    const float* Emb   = (const float*)d_in[1];
    const float* W     = (const float*)d_in[2];
    const float* U     = (const float*)d_in[3];
    const float* bias  = (const float*)d_in[4];
    const float* outW  = (const float*)d_in[5];
    const float* outb  = (const float*)d_in[6];
    float* pred = (float*)d_out;

    cudaFuncSetAttribute(scan_kernel, cudaFuncAttributeMaxDynamicSharedMemorySize, SM_TOTAL);
    cudaFuncSetAttribute(ew_gemm2, cudaFuncAttributeMaxDynamicSharedMemorySize, EW_SMEM);

    reset_kernel<<<256, 256>>>(words);
    ew_gemm2<<<dim3((NDICT + 127) / 128, NGATE / 128), 256, EW_SMEM>>>(Emb, W, bias);
    scan_kernel<<<NBLK, 128, SM_TOTAL>>>(U);
    out_kernel<<<256, 128>>>(outW, outb, pred);
}